// round 1
// baseline (speedup 1.0000x reference)
#include <cuda_runtime.h>
#include <math.h>
#include <float.h>

#define Nn   2000
#define Aa   16
#define OBSd 64
#define Hh   128
#define Ee   16000
#define NITER 8
#define IN_DIM 80   /* OBS + A */
#define G3     384  /* 3*H */

/* ---------------- scratch (static device globals; no allocs) ------------- */
__device__ float g_inp[Nn*IN_DIM];
__device__ float g_gi[Nn*G3];
__device__ float g_gh[Nn*G3];
__device__ float g_h[Nn*Hh];
__device__ float g_s[Ee*256];
__device__ float g_act0[Ee*256];
__device__ float g_act1[Ee*256];
__device__ float g_M[Ee*2*Aa];       /* [e][0]=M[ei,ej] (into i), [e][1]=M[ej,ei] (into j) */
__device__ float g_S[2*Nn*Aa];       /* ping-pong incoming-message sums */
__device__ int   g_map[Nn*Nn];       /* pair -> representative edge id */
__device__ int   g_isrep[Ee];
__device__ int   g_aidx[Nn];
__device__ int   g_best[Nn];
__device__ float g_qmax;

/* ---------------- init: clear map/M/S/best/qmax -------------------------- */
__global__ void k_init() {
    int idx = blockIdx.x*blockDim.x + threadIdx.x;
    int stride = gridDim.x*blockDim.x;
    for (int i = idx; i < Nn*Nn; i += stride)   g_map[i] = 0x7fffffff;
    for (int i = idx; i < Ee*2*Aa; i += stride) g_M[i]   = 0.f;
    for (int i = idx; i < 2*Nn*Aa; i += stride) g_S[i]   = 0.f;
    for (int i = idx; i < Nn; i += stride)      g_best[i] = -1;
    if (idx == 0) g_qmax = 0.f;
}

__global__ void k_mapbuild(const int* __restrict__ edges) {
    int e = blockIdx.x*blockDim.x + threadIdx.x;
    if (e >= Ee) return;
    int i = edges[2*e], j = edges[2*e+1];
    atomicMin(&g_map[i*Nn + j], e);
}

__global__ void k_isrep(const int* __restrict__ edges) {
    int e = blockIdx.x*blockDim.x + threadIdx.x;
    if (e >= Ee) return;
    int i = edges[2*e], j = edges[2*e+1];
    g_isrep[e] = (g_map[i*Nn + j] == e) ? 1 : 0;
}

/* ---------------- encoder input concat ----------------------------------- */
__global__ void k_concat(const float* __restrict__ x, const float* __restrict__ pa) {
    int idx = blockIdx.x*blockDim.x + threadIdx.x;
    if (idx >= Nn*IN_DIM) return;
    int n = idx / IN_DIM, c = idx % IN_DIM;
    g_inp[idx] = (c < OBSd) ? x[n*OBSd + c] : pa[n*Aa + (c - OBSd)];
}

/* ---------------- generic fp32 GEMM: C = act(X @ W^T + b) * scale -------- */
#define BM 64
#define BN 64
#define BK 16
__global__ void k_gemm(const float* __restrict__ X, const float* __restrict__ W,
                       const float* __restrict__ bias, float* __restrict__ C,
                       int M, int N, int K, int relu, float scale, int accum)
{
    __shared__ __align__(16) float Xs[BK][BM+4];
    __shared__ __align__(16) float Ws[BK][BN+4];
    const int tid = threadIdx.x;
    const int tx = tid & 15;
    const int ty = tid >> 4;
    const int bm = blockIdx.y * BM;
    const int bn = blockIdx.x * BN;
    const int lm = tid >> 2;
    const int lk = (tid & 3) << 2;

    float acc[4][4];
#pragma unroll
    for (int i = 0; i < 4; i++)
#pragma unroll
        for (int j = 0; j < 4; j++) acc[i][j] = 0.f;

    for (int k0 = 0; k0 < K; k0 += BK) {
        float4 xv = make_float4(0.f,0.f,0.f,0.f);
        float4 wv = make_float4(0.f,0.f,0.f,0.f);
        int gm = bm + lm;
        if (gm < M) xv = *reinterpret_cast<const float4*>(X + (size_t)gm*K + k0 + lk);
        int gn = bn + lm;
        if (gn < N) wv = *reinterpret_cast<const float4*>(W + (size_t)gn*K + k0 + lk);
        Xs[lk+0][lm] = xv.x; Xs[lk+1][lm] = xv.y; Xs[lk+2][lm] = xv.z; Xs[lk+3][lm] = xv.w;
        Ws[lk+0][lm] = wv.x; Ws[lk+1][lm] = wv.y; Ws[lk+2][lm] = wv.z; Ws[lk+3][lm] = wv.w;
        __syncthreads();
#pragma unroll
        for (int k = 0; k < BK; k++) {
            float4 a4 = *reinterpret_cast<const float4*>(&Xs[k][ty << 2]);
            float4 b4 = *reinterpret_cast<const float4*>(&Ws[k][tx << 2]);
            float ar[4] = {a4.x, a4.y, a4.z, a4.w};
            float br[4] = {b4.x, b4.y, b4.z, b4.w};
#pragma unroll
            for (int i = 0; i < 4; i++)
#pragma unroll
                for (int j = 0; j < 4; j++)
                    acc[i][j] = fmaf(ar[i], br[j], acc[i][j]);
        }
        __syncthreads();
    }
#pragma unroll
    for (int i = 0; i < 4; i++) {
        int m = bm + (ty << 2) + i;
        if (m >= M) continue;
#pragma unroll
        for (int j = 0; j < 4; j++) {
            int n = bn + (tx << 2) + j;
            if (n >= N) continue;
            float v = acc[i][j] + bias[n];
            if (relu) v = fmaxf(v, 0.f);
            v *= scale;
            if (accum) C[(size_t)m*N + n] += v;
            else       C[(size_t)m*N + n] = v;
        }
    }
}

/* ---------------- GRU elementwise combine -------------------------------- */
__global__ void k_gru(const float* __restrict__ hprev, float* __restrict__ out_h) {
    int idx = blockIdx.x*blockDim.x + threadIdx.x;
    if (idx >= Nn*Hh) return;
    int n = idx / Hh, d = idx % Hh;
    const float* gi = g_gi + n*G3;
    const float* gh = g_gh + n*G3;
    float r = 1.f/(1.f + expf(-(gi[d]        + gh[d])));
    float z = 1.f/(1.f + expf(-(gi[Hh+d]     + gh[Hh+d])));
    float t = tanhf(gi[2*Hh+d] + r*gh[2*Hh+d]);
    float hp = hprev[idx];
    float h = (1.f - z)*t + z*hp;
    g_h[idx] = h;
    out_h[idx] = h;
}

/* ---------------- gather edge features s_ij / s_ji ----------------------- */
__global__ void k_gather(const int* __restrict__ edges, int rev) {
    int idx = blockIdx.x*blockDim.x + threadIdx.x;
    if (idx >= Ee*64) return;
    int e = idx >> 6;
    int c = (idx & 63) << 2;
    int i = edges[2*e], j = edges[2*e+1];
    int a = rev ? j : i;
    int b = rev ? i : j;
    int node = (c < Hh) ? a : b;
    int cc   = (c < Hh) ? c : c - Hh;
    float4 v = *reinterpret_cast<const float4*>(g_h + node*Hh + cc);
    *reinterpret_cast<float4*>(g_s + (size_t)e*256 + c) = v;
}

/* ---------------- message update (one warp per edge) --------------------- */
__global__ void k_msg(const int* __restrict__ edges, const float* __restrict__ u,
                      const float* __restrict__ p, int cur) {
    int w = (blockIdx.x*blockDim.x + threadIdx.x) >> 5;
    if (w >= Ee) return;
    int lane = threadIdx.x & 31;
    int b = lane & 15;
    const float* S = g_S + cur*Nn*Aa;
    int i = edges[2*w], j = edges[2*w+1];
    float Mi = g_M[(w*2 + 0)*Aa + b];                 /* M[ei,ej] */
    float Mj = g_M[(w*2 + 1)*Aa + b];                 /* M[ej,ei] */
    float base_i = u[i*Aa + b] + S[i*Aa + b] - Mi;
    float base_j = u[j*Aa + b] + S[j*Aa + b] - Mj;
    const float* pe = p + (size_t)w*256;
    float mtj = -FLT_MAX, colmax = -FLT_MAX;
#pragma unroll
    for (int a2 = 0; a2 < 16; a2++) {
        float pab = pe[a2*16 + b];
        float bia = __shfl_sync(0xffffffffu, base_i, a2, 16);
        mtj    = fmaxf(mtj, pab + bia);
        colmax = fmaxf(colmax, pab);
    }
    float mti = colmax + base_j;
    float s1 = mtj, s2 = mti;
#pragma unroll
    for (int m = 8; m; m >>= 1) {
        s1 += __shfl_xor_sync(0xffffffffu, s1, m, 16);
        s2 += __shfl_xor_sync(0xffffffffu, s2, m, 16);
    }
    mtj -= s1 * (1.f/16.f);
    mti -= s2 * (1.f/16.f);
    if (lane < 16) {
        g_M[(w*2 + 1)*Aa + b] = mtj;   /* M[ej,ei] = msg_to_j */
        g_M[(w*2 + 0)*Aa + b] = mti;   /* M[ei,ej] = msg_to_i */
    }
}

/* ---------------- scatter S (representatives only) ----------------------- */
__global__ void k_scatter(const int* __restrict__ edges, int nxt) {
    int idx = blockIdx.x*blockDim.x + threadIdx.x;
    if (idx >= Ee*Aa) return;
    int e = idx >> 4, a = idx & 15;
    if (!g_isrep[e]) return;
    int i = edges[2*e], j = edges[2*e+1];
    float* S = g_S + nxt*Nn*Aa;
    atomicAdd(&S[i*Aa + a], g_M[(e*2 + 0)*Aa + a]);
    atomicAdd(&S[j*Aa + a], g_M[(e*2 + 1)*Aa + a]);
}

/* ---------------- per-iteration argmax + q update (single block) --------- */
__global__ void k_qstep(const int* __restrict__ edges, const float* __restrict__ u,
                        const float* __restrict__ p, int nxt) {
    const int tid = threadIdx.x;
    const float* S = g_S + nxt*Nn*Aa;
    float* Sz = g_S + (1 - nxt)*Nn*Aa;
    for (int n = tid; n < Nn; n += 1024) {
        float best = -FLT_MAX; int bi = 0;
#pragma unroll
        for (int a = 0; a < Aa; a++) {
            float v = u[n*Aa + a] + S[n*Aa + a];
            if (v > best) { best = v; bi = a; }
        }
        g_aidx[n] = bi;
    }
    __syncthreads();
    float local = 0.f;
    for (int n = tid; n < Nn; n += 1024) local += u[n*Aa + g_aidx[n]];
    for (int e = tid; e < Ee; e += 1024) {
        int i = edges[2*e], j = edges[2*e+1];
        local += p[(size_t)e*256 + g_aidx[i]*Aa + g_aidx[j]];
    }
    __shared__ float red[1024];
    __shared__ int better;
    red[tid] = local;
    __syncthreads();
    for (int s = 512; s > 0; s >>= 1) {
        if (tid < s) red[tid] += red[tid + s];
        __syncthreads();
    }
    if (tid == 0) {
        float q = red[0];
        if (q > g_qmax) { g_qmax = q; better = 1; } else better = 0;
    }
    __syncthreads();
    if (better) {
        for (int n = tid; n < Nn; n += 1024) g_best[n] = g_aidx[n];
    }
    for (int idx = tid; idx < Nn*Aa; idx += 1024) Sz[idx] = 0.f;
}

/* ---------------- finalize: one-hot a + q_max ----------------------------- */
__global__ void k_final(float* __restrict__ out) {
    int idx = blockIdx.x*blockDim.x + threadIdx.x;
    if (idx >= Nn*Aa) return;
    int n = idx >> 4, a = idx & 15;
    out[idx] = (g_best[n] == a) ? 1.f : 0.f;
    if (idx == 0) out[Nn*Aa] = g_qmax;
}

/* ---------------- host side ---------------------------------------------- */
static inline void gemm(const float* X, const float* W, const float* b, float* C,
                        int M, int N, int K, int relu, float scale, int accum) {
    dim3 grid((N + BN - 1)/BN, (M + BM - 1)/BM);
    k_gemm<<<grid, 256>>>(X, W, b, C, M, N, K, relu, scale, accum);
}

extern "C" void kernel_launch(void* const* d_in, const int* in_sizes, int n_in,
                              void* d_out, int out_size) {
    const float* x    = (const float*)d_in[0];
    const float* pa   = (const float*)d_in[1];
    const float* st   = (const float*)d_in[2];   /* [1,N,H] -> [N,H] */
    const int*   edges= (const int*)  d_in[3];
    const float* wih  = (const float*)d_in[4];
    const float* whh  = (const float*)d_in[5];
    const float* bih  = (const float*)d_in[6];
    const float* bhh  = (const float*)d_in[7];
    const float* uW0  = (const float*)d_in[8];   const float* ub0 = (const float*)d_in[9];
    const float* uW1  = (const float*)d_in[10];  const float* ub1 = (const float*)d_in[11];
    const float* uW2  = (const float*)d_in[12];  const float* ub2 = (const float*)d_in[13];
    const float* pW0  = (const float*)d_in[14];  const float* pb0 = (const float*)d_in[15];
    const float* pW1  = (const float*)d_in[16];  const float* pb1 = (const float*)d_in[17];
    const float* pW2  = (const float*)d_in[18];  const float* pb2 = (const float*)d_in[19];
    const float* pW3  = (const float*)d_in[20];  const float* pb3 = (const float*)d_in[21];
    const float* pW4  = (const float*)d_in[22];  const float* pb4 = (const float*)d_in[23];

    float* out   = (float*)d_out;
    float* out_u = out + Nn*Aa + 1;                 /* 32001 */
    float* out_p = out_u + Nn*Aa;                   /* 64001 */
    float* out_h = out_p + (size_t)Ee*Aa*Aa;        /* 4160001 */

    float *inp_, *gi_, *gh_, *h_, *s_, *a0_, *a1_;
    cudaGetSymbolAddress((void**)&inp_, g_inp);
    cudaGetSymbolAddress((void**)&gi_,  g_gi);
    cudaGetSymbolAddress((void**)&gh_,  g_gh);
    cudaGetSymbolAddress((void**)&h_,   g_h);
    cudaGetSymbolAddress((void**)&s_,   g_s);
    cudaGetSymbolAddress((void**)&a0_,  g_act0);
    cudaGetSymbolAddress((void**)&a1_,  g_act1);

    /* init + duplicate-edge dedup map */
    k_init<<<4096, 1024>>>();
    k_mapbuild<<<(Ee + 255)/256, 256>>>(edges);
    k_isrep<<<(Ee + 255)/256, 256>>>(edges);

    /* GRU encoder */
    k_concat<<<(Nn*IN_DIM + 255)/256, 256>>>(x, pa);
    gemm(inp_, wih, bih, gi_, Nn, G3, IN_DIM, 0, 1.f, 0);
    gemm(st,   whh, bhh, gh_, Nn, G3, Hh,     0, 1.f, 0);
    k_gru<<<(Nn*Hh + 255)/256, 256>>>(st, out_h);

    /* utility MLP: u = mlp(h)/N  -> out_u */
    gemm(h_,  uW0, ub0, a0_,  Nn, 256, Hh,  1, 1.f, 0);
    gemm(a0_, uW1, ub1, a1_,  Nn, 256, 256, 1, 1.f, 0);
    gemm(a1_, uW2, ub2, out_u, Nn, Aa, 256, 0, 1.f/(float)Nn, 0);

    /* payoff MLP, direction i->j */
    k_gather<<<(Ee*64 + 255)/256, 256>>>(edges, 0);
    gemm(s_,  pW0, pb0, a0_,  Ee, Hh,  256, 1, 1.f, 0);
    gemm(a0_, pW1, pb1, a1_,  Ee, 256, Hh,  1, 1.f, 0);
    gemm(a1_, pW2, pb2, a0_,  Ee, 256, 256, 1, 1.f, 0);
    gemm(a0_, pW3, pb3, a1_,  Ee, Aa,  256, 1, 1.f, 0);
    gemm(a1_, pW4, pb4, out_p, Ee, 256, Aa, 0, 0.5f/(float)Ee, 0);

    /* payoff MLP, direction j->i (accumulate) */
    k_gather<<<(Ee*64 + 255)/256, 256>>>(edges, 1);
    gemm(s_,  pW0, pb0, a0_,  Ee, Hh,  256, 1, 1.f, 0);
    gemm(a0_, pW1, pb1, a1_,  Ee, 256, Hh,  1, 1.f, 0);
    gemm(a1_, pW2, pb2, a0_,  Ee, 256, 256, 1, 1.f, 0);
    gemm(a0_, pW3, pb3, a1_,  Ee, Aa,  256, 1, 1.f, 0);
    gemm(a1_, pW4, pb4, out_p, Ee, 256, Aa, 0, 0.5f/(float)Ee, 1);

    /* max-sum message passing */
    for (int t = 0; t < NITER; t++) {
        int cur = t & 1, nxt = 1 - cur;
        k_msg<<<(Ee*32 + 255)/256, 256>>>(edges, out_u, out_p, cur);
        k_scatter<<<(Ee*Aa + 255)/256, 256>>>(edges, nxt);
        k_qstep<<<1, 1024>>>(edges, out_u, out_p, nxt);
    }

    k_final<<<(Nn*Aa + 255)/256, 256>>>(out);
}

// round 3
// speedup vs baseline: 1.5756x; 1.5756x over previous
#include <cuda_runtime.h>
#include <math.h>
#include <float.h>

#define Nn   2000
#define Aa   16
#define OBSd 64
#define Hh   128
#define Ee   16000
#define NITER 8
#define IN_DIM 80
#define G3    384
#define E2    (2*Ee)

/* ---------------- scratch (static device globals) ------------------------ */
__device__ __align__(16) float g_inp[Nn*IN_DIM];
__device__ __align__(16) float g_gi[Nn*G3];
__device__ __align__(16) float g_gh[Nn*G3];
__device__ __align__(16) float g_h[Nn*Hh];
__device__ __align__(16) float g_hA[Nn*Hh];
__device__ __align__(16) float g_hB[Nn*Hh];
__device__ __align__(16) float g_bufA[(size_t)E2*256];
__device__ __align__(16) float g_bufB[(size_t)E2*256];
__device__ __align__(16) float g_y3[E2*16];
__device__ __align__(16) float g_z[Ee*16];
__device__ __align__(16) float g_M[Ee*2*Aa];
__device__ __align__(16) float g_S[2*Nn*Aa];
__device__ int   g_map[Nn*Nn];
__device__ int   g_isrep[Ee];
__device__ int   g_aidx[Nn];
__device__ int   g_best[Nn];
__device__ float g_part[64];
__device__ float g_qmax;
__device__ int   g_better;

/* ---------------- init ---------------------------------------------------- */
__global__ void k_init() {
    int idx = blockIdx.x*blockDim.x + threadIdx.x;
    int stride = gridDim.x*blockDim.x;
    for (int i = idx; i < Nn*Nn; i += stride)   g_map[i] = 0x7fffffff;
    for (int i = idx; i < Ee*2*Aa; i += stride) g_M[i]   = 0.f;
    for (int i = idx; i < 2*Nn*Aa; i += stride) g_S[i]   = 0.f;
    for (int i = idx; i < Nn; i += stride)      g_best[i] = -1;
    if (idx == 0) g_qmax = 0.f;
}

__global__ void k_mapbuild(const int* __restrict__ edges) {
    int e = blockIdx.x*blockDim.x + threadIdx.x;
    if (e >= Ee) return;
    atomicMin(&g_map[edges[2*e]*Nn + edges[2*e+1]], e);
}

__global__ void k_isrep(const int* __restrict__ edges) {
    int e = blockIdx.x*blockDim.x + threadIdx.x;
    if (e >= Ee) return;
    g_isrep[e] = (g_map[edges[2*e]*Nn + edges[2*e+1]] == e) ? 1 : 0;
}

/* ---------------- encoder input concat ------------------------------------ */
__global__ void k_concat(const float* __restrict__ x, const float* __restrict__ pa) {
    int idx = blockIdx.x*blockDim.x + threadIdx.x;
    if (idx >= Nn*IN_DIM) return;
    int n = idx / IN_DIM, c = idx % IN_DIM;
    g_inp[idx] = (c < OBSd) ? x[n*OBSd + c] : pa[n*Aa + (c - OBSd)];
}

/* ---------------- 128x128x8 double-buffered SGEMM ------------------------ */
/* C[M,N] = epi( X[M,K](lda) @ W[N,K](ldw)^T )                               */
#define BM 128
#define BN 128
#define BK 8

__global__ __launch_bounds__(256,2)
void k_gemm128(const float* __restrict__ X, int lda,
               const float* __restrict__ W, int ldw,
               const float* __restrict__ bias, float* __restrict__ C,
               int M, int N, int K, int relu, float scale, float bias_mult,
               int vec_store)
{
    __shared__ __align__(16) float As[2][BK][BM+4];
    __shared__ __align__(16) float Bs[2][BK][BN+4];
    const int t   = threadIdx.x;
    const int bm  = blockIdx.y * BM;
    const int bn  = blockIdx.x * BN;
    const int lrow = t >> 1;
    const int lcol = (t & 1) << 2;
    const int tx = t & 15, ty = t >> 4;
    const int cx0 = tx << 2, cx1 = 64 + (tx << 2);
    const int ry0 = ty << 2, ry1 = 64 + (ty << 2);

    float acc[8][8];
#pragma unroll
    for (int i = 0; i < 8; i++)
#pragma unroll
        for (int j = 0; j < 8; j++) acc[i][j] = 0.f;

    const bool xok = (bm + lrow) < M;
    const bool wok = (bn + lrow) < N;
    const float* Xp = X + (size_t)(bm + lrow)*lda + lcol;
    const float* Wp = W + (size_t)(bn + lrow)*ldw + lcol;
    const float4 z4 = make_float4(0.f,0.f,0.f,0.f);

    float4 xa = xok ? *reinterpret_cast<const float4*>(Xp) : z4;
    float4 wa = wok ? *reinterpret_cast<const float4*>(Wp) : z4;
    As[0][lcol+0][lrow]=xa.x; As[0][lcol+1][lrow]=xa.y; As[0][lcol+2][lrow]=xa.z; As[0][lcol+3][lrow]=xa.w;
    Bs[0][lcol+0][lrow]=wa.x; Bs[0][lcol+1][lrow]=wa.y; Bs[0][lcol+2][lrow]=wa.z; Bs[0][lcol+3][lrow]=wa.w;
    __syncthreads();

    int buf = 0;
    for (int k0 = 0; k0 < K; k0 += BK) {
        const bool more = (k0 + BK) < K;
        float4 xn = z4, wn = z4;
        if (more) {
            if (xok) xn = *reinterpret_cast<const float4*>(Xp + k0 + BK);
            if (wok) wn = *reinterpret_cast<const float4*>(Wp + k0 + BK);
        }
#pragma unroll
        for (int k = 0; k < BK; k++) {
            float4 a0 = *reinterpret_cast<const float4*>(&As[buf][k][ry0]);
            float4 a1 = *reinterpret_cast<const float4*>(&As[buf][k][ry1]);
            float4 b0 = *reinterpret_cast<const float4*>(&Bs[buf][k][cx0]);
            float4 b1 = *reinterpret_cast<const float4*>(&Bs[buf][k][cx1]);
            float ar[8] = {a0.x,a0.y,a0.z,a0.w,a1.x,a1.y,a1.z,a1.w};
            float br[8] = {b0.x,b0.y,b0.z,b0.w,b1.x,b1.y,b1.z,b1.w};
#pragma unroll
            for (int i = 0; i < 8; i++)
#pragma unroll
                for (int j = 0; j < 8; j++)
                    acc[i][j] = fmaf(ar[i], br[j], acc[i][j]);
        }
        if (more) {
            int nb = buf ^ 1;
            As[nb][lcol+0][lrow]=xn.x; As[nb][lcol+1][lrow]=xn.y; As[nb][lcol+2][lrow]=xn.z; As[nb][lcol+3][lrow]=xn.w;
            Bs[nb][lcol+0][lrow]=wn.x; Bs[nb][lcol+1][lrow]=wn.y; Bs[nb][lcol+2][lrow]=wn.z; Bs[nb][lcol+3][lrow]=wn.w;
            __syncthreads();
            buf = nb;
        }
    }

    float4 bv0 = *reinterpret_cast<const float4*>(&bias[bn + cx0]);
    float4 bv1 = *reinterpret_cast<const float4*>(&bias[bn + cx1]);
#pragma unroll
    for (int ii = 0; ii < 8; ii++) {
        int r = bm + ((ii < 4) ? (ry0 + ii) : (ry1 + ii - 4));
        if (r >= M) continue;
        float o[8];
        o[0]=acc[ii][0]+bias_mult*bv0.x; o[1]=acc[ii][1]+bias_mult*bv0.y;
        o[2]=acc[ii][2]+bias_mult*bv0.z; o[3]=acc[ii][3]+bias_mult*bv0.w;
        o[4]=acc[ii][4]+bias_mult*bv1.x; o[5]=acc[ii][5]+bias_mult*bv1.y;
        o[6]=acc[ii][6]+bias_mult*bv1.z; o[7]=acc[ii][7]+bias_mult*bv1.w;
        if (relu) {
#pragma unroll
            for (int j = 0; j < 8; j++) o[j] = fmaxf(o[j], 0.f);
        }
#pragma unroll
        for (int j = 0; j < 8; j++) o[j] *= scale;
        if (vec_store) {
            *reinterpret_cast<float4*>(&C[(size_t)r*N + bn + cx0]) = make_float4(o[0],o[1],o[2],o[3]);
            *reinterpret_cast<float4*>(&C[(size_t)r*N + bn + cx1]) = make_float4(o[4],o[5],o[6],o[7]);
        } else {
            float* c0 = &C[(size_t)r*N + bn + cx0];
            float* c1 = &C[(size_t)r*N + bn + cx1];
            c0[0]=o[0]; c0[1]=o[1]; c0[2]=o[2]; c0[3]=o[3];
            c1[0]=o[4]; c1[1]=o[5]; c1[2]=o[6]; c1[3]=o[7];
        }
    }
}

/* ---------------- skinny GEMM, N=16 fixed --------------------------------- */
__global__ __launch_bounds__(256,4)
void k_gemm16(const float* __restrict__ X, int lda,
              const float* __restrict__ W, int ldw,
              const float* __restrict__ bias, float* __restrict__ C,
              int M, int K, int relu, float scale)
{
    __shared__ __align__(16) float As[16][BM+4];
    __shared__ float Bs[16][17];
    const int t = threadIdx.x;
    const int bm = blockIdx.x * BM;
    const int arow = t >> 1, acol = (t & 1) << 3;
    const int tx = t & 15, ty = t >> 4;
    const bool xok = (bm + arow) < M;
    const float4 z4 = make_float4(0.f,0.f,0.f,0.f);

    float acc[8];
#pragma unroll
    for (int i = 0; i < 8; i++) acc[i] = 0.f;

    for (int k0 = 0; k0 < K; k0 += 16) {
        float4 v0 = z4, v1 = z4;
        if (xok) {
            v0 = *reinterpret_cast<const float4*>(X + (size_t)(bm+arow)*lda + k0 + acol);
            v1 = *reinterpret_cast<const float4*>(X + (size_t)(bm+arow)*lda + k0 + acol + 4);
        }
        float4 wv = z4;
        int wr = t >> 2, wc = (t & 3) << 2;
        if (t < 64) wv = *reinterpret_cast<const float4*>(W + (size_t)wr*ldw + k0 + wc);
        __syncthreads();
        As[acol+0][arow]=v0.x; As[acol+1][arow]=v0.y; As[acol+2][arow]=v0.z; As[acol+3][arow]=v0.w;
        As[acol+4][arow]=v1.x; As[acol+5][arow]=v1.y; As[acol+6][arow]=v1.z; As[acol+7][arow]=v1.w;
        if (t < 64) { Bs[wc+0][wr]=wv.x; Bs[wc+1][wr]=wv.y; Bs[wc+2][wr]=wv.z; Bs[wc+3][wr]=wv.w; }
        __syncthreads();
#pragma unroll
        for (int k = 0; k < 16; k++) {
            float b = Bs[k][tx];
            float4 a0 = *reinterpret_cast<const float4*>(&As[k][ty*8]);
            float4 a1 = *reinterpret_cast<const float4*>(&As[k][ty*8+4]);
            acc[0]=fmaf(a0.x,b,acc[0]); acc[1]=fmaf(a0.y,b,acc[1]);
            acc[2]=fmaf(a0.z,b,acc[2]); acc[3]=fmaf(a0.w,b,acc[3]);
            acc[4]=fmaf(a1.x,b,acc[4]); acc[5]=fmaf(a1.y,b,acc[5]);
            acc[6]=fmaf(a1.z,b,acc[6]); acc[7]=fmaf(a1.w,b,acc[7]);
        }
        __syncthreads();
    }
    float bb = bias[tx];
#pragma unroll
    for (int i = 0; i < 8; i++) {
        int r = bm + ty*8 + i;
        if (r >= M) continue;
        float v = acc[i] + bb;
        if (relu) v = fmaxf(v, 0.f);
        C[(size_t)r*16 + tx] = v * scale;
    }
}

/* ---------------- GRU elementwise ----------------------------------------- */
__global__ void k_gru(const float* __restrict__ hprev, float* __restrict__ out_h) {
    int idx = blockIdx.x*blockDim.x + threadIdx.x;
    if (idx >= Nn*Hh) return;
    int n = idx / Hh, d = idx % Hh;
    const float* gi = g_gi + n*G3;
    const float* gh = g_gh + n*G3;
    float r = 1.f/(1.f + expf(-(gi[d]       + gh[d])));
    float z = 1.f/(1.f + expf(-(gi[Hh+d]    + gh[Hh+d])));
    float t = tanhf(gi[2*Hh+d] + r*gh[2*Hh+d]);
    float h = (1.f - z)*t + z*hprev[idx];
    g_h[idx] = h;
    out_h[idx] = h;
}

/* ---------------- p-layer0: act0 = relu(hA[a] + hB[b] + b0) --------------- */
__global__ void k_edge0(const int* __restrict__ edges, const float* __restrict__ b0) {
    int idx = blockIdx.x*blockDim.x + threadIdx.x;
    if (idx >= E2*32) return;
    int r = idx >> 5;
    int c = (idx & 31) << 2;
    int e = (r < Ee) ? r : r - Ee;
    int i = edges[2*e], j = edges[2*e+1];
    int na = (r < Ee) ? i : j;
    int nb = (r < Ee) ? j : i;
    float4 a = *reinterpret_cast<const float4*>(&g_hA[na*Hh + c]);
    float4 b = *reinterpret_cast<const float4*>(&g_hB[nb*Hh + c]);
    float4 bb = *reinterpret_cast<const float4*>(&b0[c]);
    float4 o;
    o.x = fmaxf(a.x + b.x + bb.x, 0.f);
    o.y = fmaxf(a.y + b.y + bb.y, 0.f);
    o.z = fmaxf(a.z + b.z + bb.z, 0.f);
    o.w = fmaxf(a.w + b.w + bb.w, 0.f);
    *reinterpret_cast<float4*>(&g_bufA[(size_t)r*Hh + c]) = o;
}

/* ---------------- z = y3_ij + y3_ji ---------------------------------------- */
__global__ void k_sum16() {
    int idx = blockIdx.x*blockDim.x + threadIdx.x;
    if (idx >= Ee*4) return;
    int e = idx >> 2, c = (idx & 3) << 2;
    float4 a = *reinterpret_cast<const float4*>(&g_y3[e*16 + c]);
    float4 b = *reinterpret_cast<const float4*>(&g_y3[(size_t)(Ee + e)*16 + c]);
    *reinterpret_cast<float4*>(&g_z[e*16 + c]) = make_float4(a.x+b.x, a.y+b.y, a.z+b.z, a.w+b.w);
}

/* ---------------- message update + fused scatter (rep edges only) --------- */
__global__ void k_msg(const int* __restrict__ edges, const float* __restrict__ u,
                      const float* __restrict__ p, int cur, int nxt) {
    int w = (blockIdx.x*blockDim.x + threadIdx.x) >> 5;
    if (w >= Ee) return;
    if (!g_isrep[w]) return;
    int lane = threadIdx.x & 31;
    int b = lane & 15;
    const float* S  = g_S + cur*Nn*Aa;
    float*       Sn = g_S + nxt*Nn*Aa;
    int i = edges[2*w], j = edges[2*w+1];
    float Mi = g_M[(w*2 + 0)*Aa + b];
    float Mj = g_M[(w*2 + 1)*Aa + b];
    float base_i = u[i*Aa + b] + S[i*Aa + b] - Mi;
    float base_j = u[j*Aa + b] + S[j*Aa + b] - Mj;
    const float* pe = p + (size_t)w*256;
    float mtj = -FLT_MAX, colmax = -FLT_MAX;
#pragma unroll
    for (int a2 = 0; a2 < 16; a2++) {
        float pab = pe[a2*16 + b];
        float bia = __shfl_sync(0xffffffffu, base_i, a2, 16);
        mtj    = fmaxf(mtj, pab + bia);
        colmax = fmaxf(colmax, pab);
    }
    float mti = colmax + base_j;
    float s1 = mtj, s2 = mti;
#pragma unroll
    for (int m = 8; m; m >>= 1) {
        s1 += __shfl_xor_sync(0xffffffffu, s1, m, 16);
        s2 += __shfl_xor_sync(0xffffffffu, s2, m, 16);
    }
    mtj -= s1 * (1.f/16.f);
    mti -= s2 * (1.f/16.f);
    if (lane < 16) {
        g_M[(w*2 + 1)*Aa + b] = mtj;
        g_M[(w*2 + 0)*Aa + b] = mti;
        atomicAdd(&Sn[i*Aa + b], mti);
        atomicAdd(&Sn[j*Aa + b], mtj);
    }
}

/* ---------------- per-node argmax + zero other S buffer ------------------- */
__global__ void k_argmax(const float* __restrict__ u, int nxt) {
    int idx = blockIdx.x*blockDim.x + threadIdx.x;
    const float* S = g_S + nxt*Nn*Aa;
    float* Sz = g_S + (1 - nxt)*Nn*Aa;
    if (idx < Nn) {
        float best = -FLT_MAX; int bi = 0;
#pragma unroll
        for (int a = 0; a < Aa; a++) {
            float v = u[idx*Aa + a] + S[idx*Aa + a];
            if (v > best) { best = v; bi = a; }
        }
        g_aidx[idx] = bi;
    }
    if (idx < Nn*Aa) Sz[idx] = 0.f;
}

/* ---------------- q partial sums (64 blocks, fixed assignment) ------------ */
__global__ void k_qpart(const int* __restrict__ edges, const float* __restrict__ u,
                        const float* __restrict__ p) {
    __shared__ float red[256];
    int tid = threadIdx.x, bid = blockIdx.x;
    int gt = bid*256 + tid;
    float local = 0.f;
    for (int n = gt; n < Nn; n += 64*256) local += u[n*Aa + g_aidx[n]];
    for (int e = gt; e < Ee; e += 64*256) {
        int i = edges[2*e], j = edges[2*e+1];
        local += p[(size_t)e*256 + g_aidx[i]*Aa + g_aidx[j]];
    }
    red[tid] = local;
    __syncthreads();
    for (int s = 128; s > 0; s >>= 1) {
        if (tid < s) red[tid] += red[tid + s];
        __syncthreads();
    }
    if (tid == 0) g_part[bid] = red[0];
}

/* ---------------- q final compare + commit best --------------------------- */
__global__ void k_qfinal() {
    int tid = threadIdx.x;
    if (tid == 0) {
        float q = 0.f;
        for (int k = 0; k < 64; k++) q += g_part[k];
        if (q > g_qmax) { g_qmax = q; g_better = 1; } else g_better = 0;
    }
    __syncthreads();
    if (g_better) {
        for (int n = tid; n < Nn; n += 256) g_best[n] = g_aidx[n];
    }
}

/* ---------------- finalize ------------------------------------------------- */
__global__ void k_final(float* __restrict__ out) {
    int idx = blockIdx.x*blockDim.x + threadIdx.x;
    if (idx >= Nn*Aa) return;
    int n = idx >> 4, a = idx & 15;
    out[idx] = (g_best[n] == a) ? 1.f : 0.f;
    if (idx == 0) out[Nn*Aa] = g_qmax;
}

/* ---------------- host ----------------------------------------------------- */
static inline void gemm(const float* X, int lda, const float* W, int ldw,
                        const float* b, float* C, int M, int N, int K,
                        int relu, float scale, float bias_mult, int vec_store) {
    dim3 grid(N/BN, (M + BM - 1)/BM);
    k_gemm128<<<grid, 256>>>(X, lda, W, ldw, b, C, M, N, K, relu, scale, bias_mult, vec_store);
}

extern "C" void kernel_launch(void* const* d_in, const int* in_sizes, int n_in,
                              void* d_out, int out_size) {
    const float* x    = (const float*)d_in[0];
    const float* pa   = (const float*)d_in[1];
    const float* st   = (const float*)d_in[2];
    const int*   edges= (const int*)  d_in[3];
    const float* wih  = (const float*)d_in[4];
    const float* whh  = (const float*)d_in[5];
    const float* bih  = (const float*)d_in[6];
    const float* bhh  = (const float*)d_in[7];
    const float* uW0  = (const float*)d_in[8];   const float* ub0 = (const float*)d_in[9];
    const float* uW1  = (const float*)d_in[10];  const float* ub1 = (const float*)d_in[11];
    const float* uW2  = (const float*)d_in[12];  const float* ub2 = (const float*)d_in[13];
    const float* pW0  = (const float*)d_in[14];  const float* pb0 = (const float*)d_in[15];
    const float* pW1  = (const float*)d_in[16];  const float* pb1 = (const float*)d_in[17];
    const float* pW2  = (const float*)d_in[18];  const float* pb2 = (const float*)d_in[19];
    const float* pW3  = (const float*)d_in[20];  const float* pb3 = (const float*)d_in[21];
    const float* pW4  = (const float*)d_in[22];  const float* pb4 = (const float*)d_in[23];

    float* out   = (float*)d_out;
    float* out_u = out + Nn*Aa + 1;
    float* out_p = out_u + Nn*Aa;
    float* out_h = out_p + (size_t)Ee*Aa*Aa;

    float *inp_, *gi_, *gh_, *h_, *hA_, *hB_, *bufA_, *bufB_, *y3_, *z_;
    cudaGetSymbolAddress((void**)&inp_,  g_inp);
    cudaGetSymbolAddress((void**)&gi_,   g_gi);
    cudaGetSymbolAddress((void**)&gh_,   g_gh);
    cudaGetSymbolAddress((void**)&h_,    g_h);
    cudaGetSymbolAddress((void**)&hA_,   g_hA);
    cudaGetSymbolAddress((void**)&hB_,   g_hB);
    cudaGetSymbolAddress((void**)&bufA_, g_bufA);
    cudaGetSymbolAddress((void**)&bufB_, g_bufB);
    cudaGetSymbolAddress((void**)&y3_,   g_y3);
    cudaGetSymbolAddress((void**)&z_,    g_z);

    /* init + dedup map */
    k_init<<<4096, 1024>>>();
    k_mapbuild<<<(Ee + 255)/256, 256>>>(edges);
    k_isrep<<<(Ee + 255)/256, 256>>>(edges);

    /* GRU encoder */
    k_concat<<<(Nn*IN_DIM + 255)/256, 256>>>(x, pa);
    gemm(inp_, IN_DIM, wih, IN_DIM, bih, gi_, Nn, G3, IN_DIM, 0, 1.f, 1.f, 1);
    gemm(st,   Hh,     whh, Hh,     bhh, gh_, Nn, G3, Hh,     0, 1.f, 1.f, 1);
    k_gru<<<(Nn*Hh + 255)/256, 256>>>(st, out_h);

    /* utility MLP */
    gemm(h_,    Hh,  uW0, Hh,  ub0, bufA_, Nn, 256, Hh,  1, 1.f, 1.f, 1);
    gemm(bufA_, 256, uW1, 256, ub1, bufB_, Nn, 256, 256, 1, 1.f, 1.f, 1);
    k_gemm16<<<(Nn + BM - 1)/BM, 256>>>(bufB_, 256, uW2, 256, ub2, out_u, Nn, 256, 0, 1.f/(float)Nn);

    /* p-MLP layer0 factorized: hA = h@W0a^T, hB = h@W0b^T */
    gemm(h_, Hh, pW0,       2*Hh, pb0, hA_, Nn, Hh, Hh, 0, 1.f, 0.f, 1);
    gemm(h_, Hh, pW0 + Hh,  2*Hh, pb0, hB_, Nn, Hh, Hh, 0, 1.f, 0.f, 1);
    k_edge0<<<(E2*32 + 255)/256, 256>>>(edges, pb0);

    /* p-MLP layers 1-3, both directions batched (M = 2E) */
    gemm(bufA_, Hh,  pW1, Hh,  pb1, bufB_, E2, 256, Hh,  1, 1.f, 1.f, 1);
    gemm(bufB_, 256, pW2, 256, pb2, bufA_, E2, 256, 256, 1, 1.f, 1.f, 1);
    k_gemm16<<<(E2 + BM - 1)/BM, 256>>>(bufA_, 256, pW3, 256, pb3, y3_, E2, 256, 1, 1.f);

    /* layer4 linear-merge: p = (W4 @ (y_ij + y_ji) + 2 b4) * 0.5/E */
    k_sum16<<<(Ee*4 + 255)/256, 256>>>();
    /* out_p = d_out + 64001 floats -> NOT 16B aligned: scalar stores */
    gemm(z_, 16, pW4, 16, pb4, out_p, Ee, 256, 16, 0, 0.5f/(float)Ee, 2.f, 0);

    /* max-sum message passing */
    for (int t = 0; t < NITER; t++) {
        int cur = t & 1, nxt = 1 - cur;
        k_msg<<<(Ee*32 + 255)/256, 256>>>(edges, out_u, out_p, cur, nxt);
        k_argmax<<<(Nn*Aa + 255)/256, 256>>>(out_u, nxt);
        k_qpart<<<64, 256>>>(edges, out_u, out_p);
        k_qfinal<<<1, 256>>>();
    }

    k_final<<<(Nn*Aa + 255)/256, 256>>>(out);
}

// round 4
// speedup vs baseline: 1.6026x; 1.0171x over previous
#include <cuda_runtime.h>
#include <math.h>
#include <float.h>

#define Nn   2000
#define Aa   16
#define OBSd 64
#define Hh   128
#define Ee   16000
#define NITER 8
#define IN_DIM 80
#define G3    384
#define E2    (2*Ee)

/* ---------------- f32x2 packed math helpers ------------------------------- */
#define PACK2(out, lo, hi) \
    asm("mov.b64 %0, {%1, %2};" : "=l"(out) : "f"(lo), "f"(hi))
#define DUP2(out, v) \
    asm("mov.b64 %0, {%1, %1};" : "=l"(out) : "f"(v))
#define FMA2(acc, a, b) \
    asm("fma.rn.f32x2 %0, %1, %2, %0;" : "+l"(acc) : "l"(a), "l"(b))
#define UNPACK2(lo, hi, v) \
    asm("mov.b64 {%0, %1}, %2;" : "=f"(lo), "=f"(hi) : "l"(v))

/* ---------------- scratch (static device globals) ------------------------ */
__device__ __align__(16) float g_inp[Nn*IN_DIM];
__device__ __align__(16) float g_gi[Nn*G3];
__device__ __align__(16) float g_gh[Nn*G3];
__device__ __align__(16) float g_h[Nn*Hh];
__device__ __align__(16) float g_hA[Nn*Hh];
__device__ __align__(16) float g_hB[Nn*Hh];
__device__ __align__(16) float g_bufA[(size_t)E2*256];
__device__ __align__(16) float g_bufB[(size_t)E2*256];
__device__ __align__(16) float g_y3[E2*16];
__device__ __align__(16) float g_z[Ee*16];
__device__ __align__(16) float g_M[Ee*2*Aa];
__device__ __align__(16) float g_S[2*Nn*Aa];
__device__ int   g_map[Nn*Nn];
__device__ int   g_isrep[Ee];
__device__ int   g_aidx[Nn];
__device__ int   g_best[Nn];
__device__ float g_part[64];
__device__ int   g_qctr;
__device__ float g_qmax;

/* ---------------- init ---------------------------------------------------- */
__global__ void k_init() {
    int idx = blockIdx.x*blockDim.x + threadIdx.x;
    int stride = gridDim.x*blockDim.x;
    for (int i = idx; i < Nn*Nn; i += stride)   g_map[i] = 0x7fffffff;
    for (int i = idx; i < Ee*2*Aa; i += stride) g_M[i]   = 0.f;
    for (int i = idx; i < 2*Nn*Aa; i += stride) g_S[i]   = 0.f;
    for (int i = idx; i < Nn; i += stride)      g_best[i] = -1;
    if (idx == 0) { g_qmax = 0.f; g_qctr = 0; }
}

__global__ void k_mapbuild(const int* __restrict__ edges) {
    int e = blockIdx.x*blockDim.x + threadIdx.x;
    if (e >= Ee) return;
    atomicMin(&g_map[edges[2*e]*Nn + edges[2*e+1]], e);
}

__global__ void k_isrep(const int* __restrict__ edges) {
    int e = blockIdx.x*blockDim.x + threadIdx.x;
    if (e >= Ee) return;
    g_isrep[e] = (g_map[edges[2*e]*Nn + edges[2*e+1]] == e) ? 1 : 0;
}

/* ---------------- encoder input concat ------------------------------------ */
__global__ void k_concat(const float* __restrict__ x, const float* __restrict__ pa) {
    int idx = blockIdx.x*blockDim.x + threadIdx.x;
    if (idx >= Nn*IN_DIM) return;
    int n = idx / IN_DIM, c = idx % IN_DIM;
    g_inp[idx] = (c < OBSd) ? x[n*OBSd + c] : pa[n*Aa + (c - OBSd)];
}

/* ---------------- 128x128x8 double-buffered SGEMM w/ FFMA2 ---------------- */
#define BM 128
#define BN 128
#define BK 8

__global__ __launch_bounds__(256,2)
void k_gemm128(const float* __restrict__ X, int lda,
               const float* __restrict__ W, int ldw,
               const float* __restrict__ bias, float* __restrict__ C,
               int M, int N, int K, int relu, float scale, float bias_mult,
               int vec_store)
{
    __shared__ __align__(16) float As[2][BK][BM+4];
    __shared__ __align__(16) float Bs[2][BK][BN+4];
    const int t   = threadIdx.x;
    const int bm  = blockIdx.y * BM;
    const int bn  = blockIdx.x * BN;
    const int lrow = t >> 1;
    const int lcol = (t & 1) << 2;
    const int tx = t & 15, ty = t >> 4;
    const int cx0 = tx << 2, cx1 = 64 + (tx << 2);
    const int ry0 = ty << 2, ry1 = 64 + (ty << 2);

    /* packed accumulators: pair i2 covers row pair, 8 cols */
    unsigned long long acc2[4][8];
#pragma unroll
    for (int i = 0; i < 4; i++)
#pragma unroll
        for (int j = 0; j < 8; j++) acc2[i][j] = 0ull;

    const bool xok = (bm + lrow) < M;
    const bool wok = (bn + lrow) < N;
    const float* Xp = X + (size_t)(bm + lrow)*lda + lcol;
    const float* Wp = W + (size_t)(bn + lrow)*ldw + lcol;
    const float4 z4 = make_float4(0.f,0.f,0.f,0.f);

    float4 xa = xok ? *reinterpret_cast<const float4*>(Xp) : z4;
    float4 wa = wok ? *reinterpret_cast<const float4*>(Wp) : z4;
    As[0][lcol+0][lrow]=xa.x; As[0][lcol+1][lrow]=xa.y; As[0][lcol+2][lrow]=xa.z; As[0][lcol+3][lrow]=xa.w;
    Bs[0][lcol+0][lrow]=wa.x; Bs[0][lcol+1][lrow]=wa.y; Bs[0][lcol+2][lrow]=wa.z; Bs[0][lcol+3][lrow]=wa.w;
    __syncthreads();

    int buf = 0;
    for (int k0 = 0; k0 < K; k0 += BK) {
        const bool more = (k0 + BK) < K;
        float4 xn = z4, wn = z4;
        if (more) {
            if (xok) xn = *reinterpret_cast<const float4*>(Xp + k0 + BK);
            if (wok) wn = *reinterpret_cast<const float4*>(Wp + k0 + BK);
        }
#pragma unroll
        for (int k = 0; k < BK; k++) {
            float4 a0 = *reinterpret_cast<const float4*>(&As[buf][k][ry0]);
            float4 a1 = *reinterpret_cast<const float4*>(&As[buf][k][ry1]);
            float4 b0 = *reinterpret_cast<const float4*>(&Bs[buf][k][cx0]);
            float4 b1 = *reinterpret_cast<const float4*>(&Bs[buf][k][cx1]);
            unsigned long long av[4], bd[8];
            PACK2(av[0], a0.x, a0.y);
            PACK2(av[1], a0.z, a0.w);
            PACK2(av[2], a1.x, a1.y);
            PACK2(av[3], a1.z, a1.w);
            DUP2(bd[0], b0.x); DUP2(bd[1], b0.y); DUP2(bd[2], b0.z); DUP2(bd[3], b0.w);
            DUP2(bd[4], b1.x); DUP2(bd[5], b1.y); DUP2(bd[6], b1.z); DUP2(bd[7], b1.w);
#pragma unroll
            for (int i = 0; i < 4; i++)
#pragma unroll
                for (int j = 0; j < 8; j++)
                    FMA2(acc2[i][j], av[i], bd[j]);
        }
        if (more) {
            int nb = buf ^ 1;
            As[nb][lcol+0][lrow]=xn.x; As[nb][lcol+1][lrow]=xn.y; As[nb][lcol+2][lrow]=xn.z; As[nb][lcol+3][lrow]=xn.w;
            Bs[nb][lcol+0][lrow]=wn.x; Bs[nb][lcol+1][lrow]=wn.y; Bs[nb][lcol+2][lrow]=wn.z; Bs[nb][lcol+3][lrow]=wn.w;
            __syncthreads();
            buf = nb;
        }
    }

    float4 bv0 = *reinterpret_cast<const float4*>(&bias[bn + cx0]);
    float4 bv1 = *reinterpret_cast<const float4*>(&bias[bn + cx1]);
    const float bb[8] = {bv0.x,bv0.y,bv0.z,bv0.w,bv1.x,bv1.y,bv1.z,bv1.w};

#pragma unroll
    for (int i2 = 0; i2 < 4; i2++) {
        /* row pair base: i2 0->ry0, 1->ry0+2, 2->ry1, 3->ry1+2 */
        int rbase = bm + ((i2 < 2) ? (ry0 + 2*i2) : (ry1 + 2*(i2-2)));
        float oe[8], oo[8];
#pragma unroll
        for (int j = 0; j < 8; j++) {
            UNPACK2(oe[j], oo[j], acc2[i2][j]);
            oe[j] += bias_mult*bb[j];
            oo[j] += bias_mult*bb[j];
            if (relu) { oe[j] = fmaxf(oe[j], 0.f); oo[j] = fmaxf(oo[j], 0.f); }
            oe[j] *= scale; oo[j] *= scale;
        }
#pragma unroll
        for (int half = 0; half < 2; half++) {
            int r = rbase + half;
            if (r >= M) continue;
            const float* o = half ? oo : oe;
            if (vec_store) {
                *reinterpret_cast<float4*>(&C[(size_t)r*N + bn + cx0]) = make_float4(o[0],o[1],o[2],o[3]);
                *reinterpret_cast<float4*>(&C[(size_t)r*N + bn + cx1]) = make_float4(o[4],o[5],o[6],o[7]);
            } else {
                float* c0 = &C[(size_t)r*N + bn + cx0];
                float* c1 = &C[(size_t)r*N + bn + cx1];
                c0[0]=o[0]; c0[1]=o[1]; c0[2]=o[2]; c0[3]=o[3];
                c1[0]=o[4]; c1[1]=o[5]; c1[2]=o[6]; c1[3]=o[7];
            }
        }
    }
}

/* ---------------- skinny GEMM, N=16 fixed --------------------------------- */
__global__ __launch_bounds__(256,4)
void k_gemm16(const float* __restrict__ X, int lda,
              const float* __restrict__ W, int ldw,
              const float* __restrict__ bias, float* __restrict__ C,
              int M, int K, int relu, float scale)
{
    __shared__ __align__(16) float As[16][BM+4];
    __shared__ float Bs[16][17];
    const int t = threadIdx.x;
    const int bm = blockIdx.x * BM;
    const int arow = t >> 1, acol = (t & 1) << 3;
    const int tx = t & 15, ty = t >> 4;
    const bool xok = (bm + arow) < M;
    const float4 z4 = make_float4(0.f,0.f,0.f,0.f);

    float acc[8];
#pragma unroll
    for (int i = 0; i < 8; i++) acc[i] = 0.f;

    for (int k0 = 0; k0 < K; k0 += 16) {
        float4 v0 = z4, v1 = z4;
        if (xok) {
            v0 = *reinterpret_cast<const float4*>(X + (size_t)(bm+arow)*lda + k0 + acol);
            v1 = *reinterpret_cast<const float4*>(X + (size_t)(bm+arow)*lda + k0 + acol + 4);
        }
        float4 wv = z4;
        int wr = t >> 2, wc = (t & 3) << 2;
        if (t < 64) wv = *reinterpret_cast<const float4*>(W + (size_t)wr*ldw + k0 + wc);
        __syncthreads();
        As[acol+0][arow]=v0.x; As[acol+1][arow]=v0.y; As[acol+2][arow]=v0.z; As[acol+3][arow]=v0.w;
        As[acol+4][arow]=v1.x; As[acol+5][arow]=v1.y; As[acol+6][arow]=v1.z; As[acol+7][arow]=v1.w;
        if (t < 64) { Bs[wc+0][wr]=wv.x; Bs[wc+1][wr]=wv.y; Bs[wc+2][wr]=wv.z; Bs[wc+3][wr]=wv.w; }
        __syncthreads();
#pragma unroll
        for (int k = 0; k < 16; k++) {
            float b = Bs[k][tx];
            float4 a0 = *reinterpret_cast<const float4*>(&As[k][ty*8]);
            float4 a1 = *reinterpret_cast<const float4*>(&As[k][ty*8+4]);
            acc[0]=fmaf(a0.x,b,acc[0]); acc[1]=fmaf(a0.y,b,acc[1]);
            acc[2]=fmaf(a0.z,b,acc[2]); acc[3]=fmaf(a0.w,b,acc[3]);
            acc[4]=fmaf(a1.x,b,acc[4]); acc[5]=fmaf(a1.y,b,acc[5]);
            acc[6]=fmaf(a1.z,b,acc[6]); acc[7]=fmaf(a1.w,b,acc[7]);
        }
        __syncthreads();
    }
    float bb = bias[tx];
#pragma unroll
    for (int i = 0; i < 8; i++) {
        int r = bm + ty*8 + i;
        if (r >= M) continue;
        float v = acc[i] + bb;
        if (relu) v = fmaxf(v, 0.f);
        C[(size_t)r*16 + tx] = v * scale;
    }
}

/* ---------------- GRU elementwise ----------------------------------------- */
__global__ void k_gru(const float* __restrict__ hprev, float* __restrict__ out_h) {
    int idx = blockIdx.x*blockDim.x + threadIdx.x;
    if (idx >= Nn*Hh) return;
    int n = idx / Hh, d = idx % Hh;
    const float* gi = g_gi + n*G3;
    const float* gh = g_gh + n*G3;
    float r = 1.f/(1.f + expf(-(gi[d]       + gh[d])));
    float z = 1.f/(1.f + expf(-(gi[Hh+d]    + gh[Hh+d])));
    float t = tanhf(gi[2*Hh+d] + r*gh[2*Hh+d]);
    float h = (1.f - z)*t + z*hprev[idx];
    g_h[idx] = h;
    out_h[idx] = h;
}

/* ---------------- p-layer0: act0 = relu(hA[a] + hB[b] + b0) --------------- */
__global__ void k_edge0(const int* __restrict__ edges, const float* __restrict__ b0) {
    int idx = blockIdx.x*blockDim.x + threadIdx.x;
    if (idx >= E2*32) return;
    int r = idx >> 5;
    int c = (idx & 31) << 2;
    int e = (r < Ee) ? r : r - Ee;
    int i = edges[2*e], j = edges[2*e+1];
    int na = (r < Ee) ? i : j;
    int nb = (r < Ee) ? j : i;
    float4 a = *reinterpret_cast<const float4*>(&g_hA[na*Hh + c]);
    float4 b = *reinterpret_cast<const float4*>(&g_hB[nb*Hh + c]);
    float4 bb = *reinterpret_cast<const float4*>(&b0[c]);
    float4 o;
    o.x = fmaxf(a.x + b.x + bb.x, 0.f);
    o.y = fmaxf(a.y + b.y + bb.y, 0.f);
    o.z = fmaxf(a.z + b.z + bb.z, 0.f);
    o.w = fmaxf(a.w + b.w + bb.w, 0.f);
    *reinterpret_cast<float4*>(&g_bufA[(size_t)r*Hh + c]) = o;
}

/* ---------------- z = y3_ij + y3_ji ---------------------------------------- */
__global__ void k_sum16() {
    int idx = blockIdx.x*blockDim.x + threadIdx.x;
    if (idx >= Ee*4) return;
    int e = idx >> 2, c = (idx & 3) << 2;
    float4 a = *reinterpret_cast<const float4*>(&g_y3[e*16 + c]);
    float4 b = *reinterpret_cast<const float4*>(&g_y3[(size_t)(Ee + e)*16 + c]);
    *reinterpret_cast<float4*>(&g_z[e*16 + c]) = make_float4(a.x+b.x, a.y+b.y, a.z+b.z, a.w+b.w);
}

/* ---------------- message update + fused scatter (rep edges only) --------- */
__global__ void k_msg(const int* __restrict__ edges, const float* __restrict__ u,
                      const float* __restrict__ p, int cur, int nxt) {
    int w = (blockIdx.x*blockDim.x + threadIdx.x) >> 5;
    if (w >= Ee) return;
    if (!g_isrep[w]) return;
    int lane = threadIdx.x & 31;
    int b = lane & 15;
    const float* S  = g_S + cur*Nn*Aa;
    float*       Sn = g_S + nxt*Nn*Aa;
    int i = edges[2*w], j = edges[2*w+1];
    float Mi = g_M[(w*2 + 0)*Aa + b];
    float Mj = g_M[(w*2 + 1)*Aa + b];
    float base_i = u[i*Aa + b] + S[i*Aa + b] - Mi;
    float base_j = u[j*Aa + b] + S[j*Aa + b] - Mj;
    const float* pe = p + (size_t)w*256;
    float mtj = -FLT_MAX, colmax = -FLT_MAX;
#pragma unroll
    for (int a2 = 0; a2 < 16; a2++) {
        float pab = pe[a2*16 + b];
        float bia = __shfl_sync(0xffffffffu, base_i, a2, 16);
        mtj    = fmaxf(mtj, pab + bia);
        colmax = fmaxf(colmax, pab);
    }
    float mti = colmax + base_j;
    float s1 = mtj, s2 = mti;
#pragma unroll
    for (int m = 8; m; m >>= 1) {
        s1 += __shfl_xor_sync(0xffffffffu, s1, m, 16);
        s2 += __shfl_xor_sync(0xffffffffu, s2, m, 16);
    }
    mtj -= s1 * (1.f/16.f);
    mti -= s2 * (1.f/16.f);
    if (lane < 16) {
        g_M[(w*2 + 1)*Aa + b] = mtj;
        g_M[(w*2 + 0)*Aa + b] = mti;
        atomicAdd(&Sn[i*Aa + b], mti);
        atomicAdd(&Sn[j*Aa + b], mtj);
    }
}

/* ---------------- per-node argmax + zero other S buffer ------------------- */
__global__ void k_argmax(const float* __restrict__ u, int nxt) {
    int idx = blockIdx.x*blockDim.x + threadIdx.x;
    const float* S = g_S + nxt*Nn*Aa;
    float* Sz = g_S + (1 - nxt)*Nn*Aa;
    if (idx < Nn) {
        float best = -FLT_MAX; int bi = 0;
#pragma unroll
        for (int a = 0; a < Aa; a++) {
            float v = u[idx*Aa + a] + S[idx*Aa + a];
            if (v > best) { best = v; bi = a; }
        }
        g_aidx[idx] = bi;
    }
    if (idx < Nn*Aa) Sz[idx] = 0.f;
}

/* ---------------- q partial sums + fused last-block final reduce ---------- */
__global__ void k_qstep(const int* __restrict__ edges, const float* __restrict__ u,
                        const float* __restrict__ p) {
    __shared__ float red[256];
    __shared__ int lastdone;
    int tid = threadIdx.x, bid = blockIdx.x;
    int gt = bid*256 + tid;
    float local = 0.f;
    for (int n = gt; n < Nn; n += 64*256) local += u[n*Aa + g_aidx[n]];
    for (int e = gt; e < Ee; e += 64*256) {
        int i = edges[2*e], j = edges[2*e+1];
        local += p[(size_t)e*256 + g_aidx[i]*Aa + g_aidx[j]];
    }
    red[tid] = local;
    __syncthreads();
    for (int s = 128; s > 0; s >>= 1) {
        if (tid < s) red[tid] += red[tid + s];
        __syncthreads();
    }
    if (tid == 0) {
        g_part[bid] = red[0];
        __threadfence();
        int done = atomicAdd(&g_qctr, 1);
        lastdone = (done == 63) ? 1 : 0;
    }
    __syncthreads();
    if (!lastdone) return;
    /* this is the last block: deterministic fixed-order final reduce */
    __shared__ int better;
    if (tid == 0) {
        float q = 0.f;
        for (int k = 0; k < 64; k++) q += g_part[k];
        if (q > g_qmax) { g_qmax = q; better = 1; } else better = 0;
        g_qctr = 0;
    }
    __syncthreads();
    if (better) {
        for (int n = tid; n < Nn; n += 256) g_best[n] = g_aidx[n];
    }
}

/* ---------------- finalize ------------------------------------------------- */
__global__ void k_final(float* __restrict__ out) {
    int idx = blockIdx.x*blockDim.x + threadIdx.x;
    if (idx >= Nn*Aa) return;
    int n = idx >> 4, a = idx & 15;
    out[idx] = (g_best[n] == a) ? 1.f : 0.f;
    if (idx == 0) out[Nn*Aa] = g_qmax;
}

/* ---------------- host ----------------------------------------------------- */
static inline void gemm(const float* X, int lda, const float* W, int ldw,
                        const float* b, float* C, int M, int N, int K,
                        int relu, float scale, float bias_mult, int vec_store) {
    dim3 grid(N/BN, (M + BM - 1)/BM);
    k_gemm128<<<grid, 256>>>(X, lda, W, ldw, b, C, M, N, K, relu, scale, bias_mult, vec_store);
}

extern "C" void kernel_launch(void* const* d_in, const int* in_sizes, int n_in,
                              void* d_out, int out_size) {
    const float* x    = (const float*)d_in[0];
    const float* pa   = (const float*)d_in[1];
    const float* st   = (const float*)d_in[2];
    const int*   edges= (const int*)  d_in[3];
    const float* wih  = (const float*)d_in[4];
    const float* whh  = (const float*)d_in[5];
    const float* bih  = (const float*)d_in[6];
    const float* bhh  = (const float*)d_in[7];
    const float* uW0  = (const float*)d_in[8];   const float* ub0 = (const float*)d_in[9];
    const float* uW1  = (const float*)d_in[10];  const float* ub1 = (const float*)d_in[11];
    const float* uW2  = (const float*)d_in[12];  const float* ub2 = (const float*)d_in[13];
    const float* pW0  = (const float*)d_in[14];  const float* pb0 = (const float*)d_in[15];
    const float* pW1  = (const float*)d_in[16];  const float* pb1 = (const float*)d_in[17];
    const float* pW2  = (const float*)d_in[18];  const float* pb2 = (const float*)d_in[19];
    const float* pW3  = (const float*)d_in[20];  const float* pb3 = (const float*)d_in[21];
    const float* pW4  = (const float*)d_in[22];  const float* pb4 = (const float*)d_in[23];

    float* out   = (float*)d_out;
    float* out_u = out + Nn*Aa + 1;
    float* out_p = out_u + Nn*Aa;
    float* out_h = out_p + (size_t)Ee*Aa*Aa;

    float *inp_, *gi_, *gh_, *h_, *hA_, *hB_, *bufA_, *bufB_, *y3_, *z_;
    cudaGetSymbolAddress((void**)&inp_,  g_inp);
    cudaGetSymbolAddress((void**)&gi_,   g_gi);
    cudaGetSymbolAddress((void**)&gh_,   g_gh);
    cudaGetSymbolAddress((void**)&h_,    g_h);
    cudaGetSymbolAddress((void**)&hA_,   g_hA);
    cudaGetSymbolAddress((void**)&hB_,   g_hB);
    cudaGetSymbolAddress((void**)&bufA_, g_bufA);
    cudaGetSymbolAddress((void**)&bufB_, g_bufB);
    cudaGetSymbolAddress((void**)&y3_,   g_y3);
    cudaGetSymbolAddress((void**)&z_,    g_z);

    /* init + dedup map */
    k_init<<<4096, 1024>>>();
    k_mapbuild<<<(Ee + 255)/256, 256>>>(edges);
    k_isrep<<<(Ee + 255)/256, 256>>>(edges);

    /* GRU encoder */
    k_concat<<<(Nn*IN_DIM + 255)/256, 256>>>(x, pa);
    gemm(inp_, IN_DIM, wih, IN_DIM, bih, gi_, Nn, G3, IN_DIM, 0, 1.f, 1.f, 1);
    gemm(st,   Hh,     whh, Hh,     bhh, gh_, Nn, G3, Hh,     0, 1.f, 1.f, 1);
    k_gru<<<(Nn*Hh + 255)/256, 256>>>(st, out_h);

    /* utility MLP */
    gemm(h_,    Hh,  uW0, Hh,  ub0, bufA_, Nn, 256, Hh,  1, 1.f, 1.f, 1);
    gemm(bufA_, 256, uW1, 256, ub1, bufB_, Nn, 256, 256, 1, 1.f, 1.f, 1);
    k_gemm16<<<(Nn + BM - 1)/BM, 256>>>(bufB_, 256, uW2, 256, ub2, out_u, Nn, 256, 0, 1.f/(float)Nn);

    /* p-MLP layer0 factorized: hA = h@W0a^T, hB = h@W0b^T */
    gemm(h_, Hh, pW0,       2*Hh, pb0, hA_, Nn, Hh, Hh, 0, 1.f, 0.f, 1);
    gemm(h_, Hh, pW0 + Hh,  2*Hh, pb0, hB_, Nn, Hh, Hh, 0, 1.f, 0.f, 1);
    k_edge0<<<(E2*32 + 255)/256, 256>>>(edges, pb0);

    /* p-MLP layers 1-3, both directions batched (M = 2E) */
    gemm(bufA_, Hh,  pW1, Hh,  pb1, bufB_, E2, 256, Hh,  1, 1.f, 1.f, 1);
    gemm(bufB_, 256, pW2, 256, pb2, bufA_, E2, 256, 256, 1, 1.f, 1.f, 1);
    k_gemm16<<<(E2 + BM - 1)/BM, 256>>>(bufA_, 256, pW3, 256, pb3, y3_, E2, 256, 1, 1.f);

    /* layer4 linear-merge: p = (W4 @ (y_ij + y_ji) + 2 b4) * 0.5/E */
    k_sum16<<<(Ee*4 + 255)/256, 256>>>();
    /* out_p = d_out + 64001 floats -> NOT 16B aligned: scalar stores */
    gemm(z_, 16, pW4, 16, pb4, out_p, Ee, 256, 16, 0, 0.5f/(float)Ee, 2.f, 0);

    /* max-sum message passing */
    for (int t = 0; t < NITER; t++) {
        int cur = t & 1, nxt = 1 - cur;
        k_msg<<<(Ee*32 + 255)/256, 256>>>(edges, out_u, out_p, cur, nxt);
        k_argmax<<<(Nn*Aa + 255)/256, 256>>>(out_u, nxt);
        k_qstep<<<64, 256>>>(edges, out_u, out_p);
    }

    k_final<<<(Nn*Aa + 255)/256, 256>>>(out);
}

// round 5
// speedup vs baseline: 2.2007x; 1.3732x over previous
#include <cuda_runtime.h>
#include <math.h>
#include <float.h>

#define Nn   2000
#define Aa   16
#define OBSd 64
#define Hh   128
#define Ee   16000
#define NITER 8
#define IN_DIM 80
#define G3    384
#define E2    (2*Ee)

/* ---------------- scratch (static device globals) ------------------------ */
__device__ __align__(16) float g_inp[Nn*IN_DIM];
__device__ __align__(16) float g_gi[Nn*G3];
__device__ __align__(16) float g_gh[Nn*G3];
__device__ __align__(16) float g_h[Nn*Hh];
__device__ __align__(16) float g_hA[Nn*Hh];
__device__ __align__(16) float g_hB[Nn*Hh];
__device__ __align__(16) float g_ua[Nn*256];
__device__ __align__(16) float g_ub[Nn*256];
__device__ __align__(16) float g_bufA[(size_t)E2*256];
__device__ __align__(16) float g_bufB[(size_t)E2*256];
__device__ __align__(16) float g_y3[E2*16];
__device__ __align__(16) float g_z[Ee*16];
__device__ __align__(16) float g_M[Ee*2*Aa];
__device__ __align__(16) float g_S[2*Nn*Aa];
__device__ int   g_map[Nn*Nn];
__device__ int   g_isrep[Ee];
__device__ int   g_aidx[2][Nn];
__device__ int   g_best[Nn];
__device__ float g_part[64];
__device__ int   g_qctr;
__device__ float g_qmax;

/* ---------------- init (no big map sweep) --------------------------------- */
__global__ void k_init() {
    int idx = blockIdx.x*blockDim.x + threadIdx.x;
    int stride = gridDim.x*blockDim.x;
    for (int i = idx; i < Ee*2*Aa; i += stride) g_M[i]   = 0.f;
    for (int i = idx; i < 2*Nn*Aa; i += stride) g_S[i]   = 0.f;
    for (int i = idx; i < Nn; i += stride)      g_best[i] = -1;
    if (idx == 0) { g_qmax = 0.f; g_qctr = 0; }
}

__global__ void k_clearmap(const int* __restrict__ edges) {
    int e = blockIdx.x*blockDim.x + threadIdx.x;
    if (e >= Ee) return;
    g_map[edges[2*e]*Nn + edges[2*e+1]] = 0x7fffffff;
}

__global__ void k_mapbuild(const int* __restrict__ edges) {
    int e = blockIdx.x*blockDim.x + threadIdx.x;
    if (e >= Ee) return;
    atomicMin(&g_map[edges[2*e]*Nn + edges[2*e+1]], e);
}

__global__ void k_isrep(const int* __restrict__ edges) {
    int e = blockIdx.x*blockDim.x + threadIdx.x;
    if (e >= Ee) return;
    g_isrep[e] = (g_map[edges[2*e]*Nn + edges[2*e+1]] == e) ? 1 : 0;
}

/* ---------------- encoder input concat ------------------------------------ */
__global__ void k_concat(const float* __restrict__ x, const float* __restrict__ pa) {
    int idx = blockIdx.x*blockDim.x + threadIdx.x;
    if (idx >= Nn*IN_DIM) return;
    int n = idx / IN_DIM, c = idx % IN_DIM;
    g_inp[idx] = (c < OBSd) ? x[n*OBSd + c] : pa[n*Aa + (c - OBSd)];
}

/* ---------------- 128x128x8 double-buffered SGEMM ------------------------- */
#define BM 128
#define BN 128
#define BK 8

__global__ __launch_bounds__(256,2)
void k_gemm128(const float* __restrict__ X, int lda,
               const float* __restrict__ W, int ldw,
               const float* __restrict__ bias, float* __restrict__ C,
               int M, int N, int K, int relu, float scale, float bias_mult,
               int vec_store)
{
    __shared__ __align__(16) float As[2][BK][BM+4];
    __shared__ __align__(16) float Bs[2][BK][BN+4];
    const int t   = threadIdx.x;
    const int bm  = blockIdx.y * BM;
    const int bn  = blockIdx.x * BN;
    const int lrow = t >> 1;
    const int lcol = (t & 1) << 2;
    const int tx = t & 15, ty = t >> 4;
    const int cx0 = tx << 2, cx1 = 64 + (tx << 2);
    const int ry0 = ty << 2, ry1 = 64 + (ty << 2);

    float acc[8][8];
#pragma unroll
    for (int i = 0; i < 8; i++)
#pragma unroll
        for (int j = 0; j < 8; j++) acc[i][j] = 0.f;

    const bool xok = (bm + lrow) < M;
    const bool wok = (bn + lrow) < N;
    const float* Xp = X + (size_t)(bm + lrow)*lda + lcol;
    const float* Wp = W + (size_t)(bn + lrow)*ldw + lcol;
    const float4 z4 = make_float4(0.f,0.f,0.f,0.f);

    float4 xa = xok ? *reinterpret_cast<const float4*>(Xp) : z4;
    float4 wa = wok ? *reinterpret_cast<const float4*>(Wp) : z4;
    As[0][lcol+0][lrow]=xa.x; As[0][lcol+1][lrow]=xa.y; As[0][lcol+2][lrow]=xa.z; As[0][lcol+3][lrow]=xa.w;
    Bs[0][lcol+0][lrow]=wa.x; Bs[0][lcol+1][lrow]=wa.y; Bs[0][lcol+2][lrow]=wa.z; Bs[0][lcol+3][lrow]=wa.w;
    __syncthreads();

    int buf = 0;
    for (int k0 = 0; k0 < K; k0 += BK) {
        const bool more = (k0 + BK) < K;
        float4 xn = z4, wn = z4;
        if (more) {
            if (xok) xn = *reinterpret_cast<const float4*>(Xp + k0 + BK);
            if (wok) wn = *reinterpret_cast<const float4*>(Wp + k0 + BK);
        }
#pragma unroll
        for (int k = 0; k < BK; k++) {
            float4 a0 = *reinterpret_cast<const float4*>(&As[buf][k][ry0]);
            float4 a1 = *reinterpret_cast<const float4*>(&As[buf][k][ry1]);
            float4 b0 = *reinterpret_cast<const float4*>(&Bs[buf][k][cx0]);
            float4 b1 = *reinterpret_cast<const float4*>(&Bs[buf][k][cx1]);
            float ar[8] = {a0.x,a0.y,a0.z,a0.w,a1.x,a1.y,a1.z,a1.w};
            float br[8] = {b0.x,b0.y,b0.z,b0.w,b1.x,b1.y,b1.z,b1.w};
#pragma unroll
            for (int i = 0; i < 8; i++)
#pragma unroll
                for (int j = 0; j < 8; j++)
                    acc[i][j] = fmaf(ar[i], br[j], acc[i][j]);
        }
        if (more) {
            int nb = buf ^ 1;
            As[nb][lcol+0][lrow]=xn.x; As[nb][lcol+1][lrow]=xn.y; As[nb][lcol+2][lrow]=xn.z; As[nb][lcol+3][lrow]=xn.w;
            Bs[nb][lcol+0][lrow]=wn.x; Bs[nb][lcol+1][lrow]=wn.y; Bs[nb][lcol+2][lrow]=wn.z; Bs[nb][lcol+3][lrow]=wn.w;
            __syncthreads();
            buf = nb;
        }
    }

    float4 bv0 = *reinterpret_cast<const float4*>(&bias[bn + cx0]);
    float4 bv1 = *reinterpret_cast<const float4*>(&bias[bn + cx1]);
#pragma unroll
    for (int ii = 0; ii < 8; ii++) {
        int r = bm + ((ii < 4) ? (ry0 + ii) : (ry1 + ii - 4));
        if (r >= M) continue;
        float o[8];
        o[0]=acc[ii][0]+bias_mult*bv0.x; o[1]=acc[ii][1]+bias_mult*bv0.y;
        o[2]=acc[ii][2]+bias_mult*bv0.z; o[3]=acc[ii][3]+bias_mult*bv0.w;
        o[4]=acc[ii][4]+bias_mult*bv1.x; o[5]=acc[ii][5]+bias_mult*bv1.y;
        o[6]=acc[ii][6]+bias_mult*bv1.z; o[7]=acc[ii][7]+bias_mult*bv1.w;
        if (relu) {
#pragma unroll
            for (int j = 0; j < 8; j++) o[j] = fmaxf(o[j], 0.f);
        }
#pragma unroll
        for (int j = 0; j < 8; j++) o[j] *= scale;
        if (vec_store) {
            *reinterpret_cast<float4*>(&C[(size_t)r*N + bn + cx0]) = make_float4(o[0],o[1],o[2],o[3]);
            *reinterpret_cast<float4*>(&C[(size_t)r*N + bn + cx1]) = make_float4(o[4],o[5],o[6],o[7]);
        } else {
            float* c0 = &C[(size_t)r*N + bn + cx0];
            float* c1 = &C[(size_t)r*N + bn + cx1];
            c0[0]=o[0]; c0[1]=o[1]; c0[2]=o[2]; c0[3]=o[3];
            c1[0]=o[4]; c1[1]=o[5]; c1[2]=o[6]; c1[3]=o[7];
        }
    }
}

/* ---------------- skinny GEMM, N=16 fixed --------------------------------- */
__global__ __launch_bounds__(256,4)
void k_gemm16(const float* __restrict__ X, int lda,
              const float* __restrict__ W, int ldw,
              const float* __restrict__ bias, float* __restrict__ C,
              int M, int K, int relu, float scale)
{
    __shared__ __align__(16) float As[16][BM+4];
    __shared__ float Bs[16][17];
    const int t = threadIdx.x;
    const int bm = blockIdx.x * BM;
    const int arow = t >> 1, acol = (t & 1) << 3;
    const int tx = t & 15, ty = t >> 4;
    const bool xok = (bm + arow) < M;
    const float4 z4 = make_float4(0.f,0.f,0.f,0.f);

    float acc[8];
#pragma unroll
    for (int i = 0; i < 8; i++) acc[i] = 0.f;

    for (int k0 = 0; k0 < K; k0 += 16) {
        float4 v0 = z4, v1 = z4;
        if (xok) {
            v0 = *reinterpret_cast<const float4*>(X + (size_t)(bm+arow)*lda + k0 + acol);
            v1 = *reinterpret_cast<const float4*>(X + (size_t)(bm+arow)*lda + k0 + acol + 4);
        }
        float4 wv = z4;
        int wr = t >> 2, wc = (t & 3) << 2;
        if (t < 64) wv = *reinterpret_cast<const float4*>(W + (size_t)wr*ldw + k0 + wc);
        __syncthreads();
        As[acol+0][arow]=v0.x; As[acol+1][arow]=v0.y; As[acol+2][arow]=v0.z; As[acol+3][arow]=v0.w;
        As[acol+4][arow]=v1.x; As[acol+5][arow]=v1.y; As[acol+6][arow]=v1.z; As[acol+7][arow]=v1.w;
        if (t < 64) { Bs[wc+0][wr]=wv.x; Bs[wc+1][wr]=wv.y; Bs[wc+2][wr]=wv.z; Bs[wc+3][wr]=wv.w; }
        __syncthreads();
#pragma unroll
        for (int k = 0; k < 16; k++) {
            float b = Bs[k][tx];
            float4 a0 = *reinterpret_cast<const float4*>(&As[k][ty*8]);
            float4 a1 = *reinterpret_cast<const float4*>(&As[k][ty*8+4]);
            acc[0]=fmaf(a0.x,b,acc[0]); acc[1]=fmaf(a0.y,b,acc[1]);
            acc[2]=fmaf(a0.z,b,acc[2]); acc[3]=fmaf(a0.w,b,acc[3]);
            acc[4]=fmaf(a1.x,b,acc[4]); acc[5]=fmaf(a1.y,b,acc[5]);
            acc[6]=fmaf(a1.z,b,acc[6]); acc[7]=fmaf(a1.w,b,acc[7]);
        }
        __syncthreads();
    }
    float bb = bias[tx];
#pragma unroll
    for (int i = 0; i < 8; i++) {
        int r = bm + ty*8 + i;
        if (r >= M) continue;
        float v = acc[i] + bb;
        if (relu) v = fmaxf(v, 0.f);
        C[(size_t)r*16 + tx] = v * scale;
    }
}

/* ---------------- GRU elementwise ----------------------------------------- */
__global__ void k_gru(const float* __restrict__ hprev, float* __restrict__ out_h) {
    int idx = blockIdx.x*blockDim.x + threadIdx.x;
    if (idx >= Nn*Hh) return;
    int n = idx / Hh, d = idx % Hh;
    const float* gi = g_gi + n*G3;
    const float* gh = g_gh + n*G3;
    float r = 1.f/(1.f + expf(-(gi[d]       + gh[d])));
    float z = 1.f/(1.f + expf(-(gi[Hh+d]    + gh[Hh+d])));
    float t = tanhf(gi[2*Hh+d] + r*gh[2*Hh+d]);
    float h = (1.f - z)*t + z*hprev[idx];
    g_h[idx] = h;
    out_h[idx] = h;
}

/* ---------------- p-layer0: act0 = relu(hA[a] + hB[b] + b0) --------------- */
__global__ void k_edge0(const int* __restrict__ edges, const float* __restrict__ b0) {
    int idx = blockIdx.x*blockDim.x + threadIdx.x;
    if (idx >= E2*32) return;
    int r = idx >> 5;
    int c = (idx & 31) << 2;
    int e = (r < Ee) ? r : r - Ee;
    int i = edges[2*e], j = edges[2*e+1];
    int na = (r < Ee) ? i : j;
    int nb = (r < Ee) ? j : i;
    float4 a = *reinterpret_cast<const float4*>(&g_hA[na*Hh + c]);
    float4 b = *reinterpret_cast<const float4*>(&g_hB[nb*Hh + c]);
    float4 bb = *reinterpret_cast<const float4*>(&b0[c]);
    float4 o;
    o.x = fmaxf(a.x + b.x + bb.x, 0.f);
    o.y = fmaxf(a.y + b.y + bb.y, 0.f);
    o.z = fmaxf(a.z + b.z + bb.z, 0.f);
    o.w = fmaxf(a.w + b.w + bb.w, 0.f);
    *reinterpret_cast<float4*>(&g_bufA[(size_t)r*Hh + c]) = o;
}

/* ---------------- z = y3_ij + y3_ji ---------------------------------------- */
__global__ void k_sum16() {
    int idx = blockIdx.x*blockDim.x + threadIdx.x;
    if (idx >= Ee*4) return;
    int e = idx >> 2, c = (idx & 3) << 2;
    float4 a = *reinterpret_cast<const float4*>(&g_y3[e*16 + c]);
    float4 b = *reinterpret_cast<const float4*>(&g_y3[(size_t)(Ee + e)*16 + c]);
    *reinterpret_cast<float4*>(&g_z[e*16 + c]) = make_float4(a.x+b.x, a.y+b.y, a.z+b.z, a.w+b.w);
}

/* ---------------- message update + fused scatter (rep edges only) --------- */
__global__ void k_msg(const int* __restrict__ edges, const float* __restrict__ u,
                      const float* __restrict__ p, int cur, int nxt) {
    int w = (blockIdx.x*blockDim.x + threadIdx.x) >> 5;
    if (w >= Ee) return;
    if (!g_isrep[w]) return;
    int lane = threadIdx.x & 31;
    int b = lane & 15;
    const float* S  = g_S + cur*Nn*Aa;
    float*       Sn = g_S + nxt*Nn*Aa;
    int i = edges[2*w], j = edges[2*w+1];
    float Mi = g_M[(w*2 + 0)*Aa + b];
    float Mj = g_M[(w*2 + 1)*Aa + b];
    float base_i = u[i*Aa + b] + S[i*Aa + b] - Mi;
    float base_j = u[j*Aa + b] + S[j*Aa + b] - Mj;
    const float* pe = p + (size_t)w*256;
    float mtj = -FLT_MAX, colmax = -FLT_MAX;
#pragma unroll
    for (int a2 = 0; a2 < 16; a2++) {
        float pab = pe[a2*16 + b];
        float bia = __shfl_sync(0xffffffffu, base_i, a2, 16);
        mtj    = fmaxf(mtj, pab + bia);
        colmax = fmaxf(colmax, pab);
    }
    float mti = colmax + base_j;
    float s1 = mtj, s2 = mti;
#pragma unroll
    for (int m = 8; m; m >>= 1) {
        s1 += __shfl_xor_sync(0xffffffffu, s1, m, 16);
        s2 += __shfl_xor_sync(0xffffffffu, s2, m, 16);
    }
    mtj -= s1 * (1.f/16.f);
    mti -= s2 * (1.f/16.f);
    if (lane < 16) {
        g_M[(w*2 + 1)*Aa + b] = mtj;
        g_M[(w*2 + 0)*Aa + b] = mti;
        atomicAdd(&Sn[i*Aa + b], mti);
        atomicAdd(&Sn[j*Aa + b], mtj);
    }
}

/* ---------------- per-node argmax + zero other S buffer ------------------- */
__global__ void k_argmax(const float* __restrict__ u, int nxt, int ab) {
    int idx = blockIdx.x*blockDim.x + threadIdx.x;
    const float* S = g_S + nxt*Nn*Aa;
    float* Sz = g_S + (1 - nxt)*Nn*Aa;
    if (idx < Nn) {
        float best = -FLT_MAX; int bi = 0;
#pragma unroll
        for (int a = 0; a < Aa; a++) {
            float v = u[idx*Aa + a] + S[idx*Aa + a];
            if (v > best) { best = v; bi = a; }
        }
        g_aidx[ab][idx] = bi;
    }
    if (idx < Nn*Aa) Sz[idx] = 0.f;
}

/* ---------------- q partial sums + fused last-block final reduce ---------- */
__global__ void k_qstep(const int* __restrict__ edges, const float* __restrict__ u,
                        const float* __restrict__ p, int ab) {
    __shared__ float red[256];
    __shared__ int lastdone;
    const int* aidx = g_aidx[ab];
    int tid = threadIdx.x, bid = blockIdx.x;
    int gt = bid*256 + tid;
    float local = 0.f;
    for (int n = gt; n < Nn; n += 64*256) local += u[n*Aa + aidx[n]];
    for (int e = gt; e < Ee; e += 64*256) {
        int i = edges[2*e], j = edges[2*e+1];
        local += p[(size_t)e*256 + aidx[i]*Aa + aidx[j]];
    }
    red[tid] = local;
    __syncthreads();
    for (int s = 128; s > 0; s >>= 1) {
        if (tid < s) red[tid] += red[tid + s];
        __syncthreads();
    }
    if (tid == 0) {
        g_part[bid] = red[0];
        __threadfence();
        int done = atomicAdd(&g_qctr, 1);
        lastdone = (done == 63) ? 1 : 0;
    }
    __syncthreads();
    if (!lastdone) return;
    __shared__ int better;
    if (tid == 0) {
        float q = 0.f;
        for (int k = 0; k < 64; k++) q += g_part[k];
        if (q > g_qmax) { g_qmax = q; better = 1; } else better = 0;
        g_qctr = 0;
    }
    __syncthreads();
    if (better) {
        for (int n = tid; n < Nn; n += 256) g_best[n] = g_aidx[ab][n];
    }
}

/* ---------------- finalize ------------------------------------------------- */
__global__ void k_final(float* __restrict__ out) {
    int idx = blockIdx.x*blockDim.x + threadIdx.x;
    if (idx >= Nn*Aa) return;
    int n = idx >> 4, a = idx & 15;
    out[idx] = (g_best[n] == a) ? 1.f : 0.f;
    if (idx == 0) out[Nn*Aa] = g_qmax;
}

/* ---------------- host ----------------------------------------------------- */
static inline void gemm(cudaStream_t st, const float* X, int lda, const float* W, int ldw,
                        const float* b, float* C, int M, int N, int K,
                        int relu, float scale, float bias_mult, int vec_store) {
    dim3 grid(N/BN, (M + BM - 1)/BM);
    k_gemm128<<<grid, 256, 0, st>>>(X, lda, W, ldw, b, C, M, N, K, relu, scale, bias_mult, vec_store);
}

extern "C" void kernel_launch(void* const* d_in, const int* in_sizes, int n_in,
                              void* d_out, int out_size) {
    const float* x    = (const float*)d_in[0];
    const float* pa   = (const float*)d_in[1];
    const float* st   = (const float*)d_in[2];
    const int*   edges= (const int*)  d_in[3];
    const float* wih  = (const float*)d_in[4];
    const float* whh  = (const float*)d_in[5];
    const float* bih  = (const float*)d_in[6];
    const float* bhh  = (const float*)d_in[7];
    const float* uW0  = (const float*)d_in[8];   const float* ub0 = (const float*)d_in[9];
    const float* uW1  = (const float*)d_in[10];  const float* ub1 = (const float*)d_in[11];
    const float* uW2  = (const float*)d_in[12];  const float* ub2 = (const float*)d_in[13];
    const float* pW0  = (const float*)d_in[14];  const float* pb0 = (const float*)d_in[15];
    const float* pW1  = (const float*)d_in[16];  const float* pb1 = (const float*)d_in[17];
    const float* pW2  = (const float*)d_in[18];  const float* pb2 = (const float*)d_in[19];
    const float* pW3  = (const float*)d_in[20];  const float* pb3 = (const float*)d_in[21];
    const float* pW4  = (const float*)d_in[22];  const float* pb4 = (const float*)d_in[23];

    float* out   = (float*)d_out;
    float* out_u = out + Nn*Aa + 1;
    float* out_p = out_u + Nn*Aa;
    float* out_h = out_p + (size_t)Ee*Aa*Aa;

    float *inp_, *gi_, *gh_, *h_, *hA_, *hB_, *ua_, *ub_, *bufA_, *bufB_, *y3_, *z_;
    cudaGetSymbolAddress((void**)&inp_,  g_inp);
    cudaGetSymbolAddress((void**)&gi_,   g_gi);
    cudaGetSymbolAddress((void**)&gh_,   g_gh);
    cudaGetSymbolAddress((void**)&h_,    g_h);
    cudaGetSymbolAddress((void**)&hA_,   g_hA);
    cudaGetSymbolAddress((void**)&hB_,   g_hB);
    cudaGetSymbolAddress((void**)&ua_,   g_ua);
    cudaGetSymbolAddress((void**)&ub_,   g_ub);
    cudaGetSymbolAddress((void**)&bufA_, g_bufA);
    cudaGetSymbolAddress((void**)&bufB_, g_bufB);
    cudaGetSymbolAddress((void**)&y3_,   g_y3);
    cudaGetSymbolAddress((void**)&z_,    g_z);

    /* streams/events created once; captured topology identical every call */
    static cudaStream_t s1 = 0, s2 = 0, s3 = 0;
    static cudaEvent_t e0 = 0, e_gh, e_gru, e_u, e_hb, e_s1, evI[NITER], evQ[NITER];
    if (!e0) {
        cudaStreamCreateWithFlags(&s1, cudaStreamNonBlocking);
        cudaStreamCreateWithFlags(&s2, cudaStreamNonBlocking);
        cudaStreamCreateWithFlags(&s3, cudaStreamNonBlocking);
        cudaEventCreateWithFlags(&e0,   cudaEventDisableTiming);
        cudaEventCreateWithFlags(&e_gh, cudaEventDisableTiming);
        cudaEventCreateWithFlags(&e_gru,cudaEventDisableTiming);
        cudaEventCreateWithFlags(&e_u,  cudaEventDisableTiming);
        cudaEventCreateWithFlags(&e_hb, cudaEventDisableTiming);
        cudaEventCreateWithFlags(&e_s1, cudaEventDisableTiming);
        for (int t = 0; t < NITER; t++) {
            cudaEventCreateWithFlags(&evI[t], cudaEventDisableTiming);
            cudaEventCreateWithFlags(&evQ[t], cudaEventDisableTiming);
        }
    }

    /* fork */
    cudaEventRecord(e0, 0);
    cudaStreamWaitEvent(s1, e0, 0);
    cudaStreamWaitEvent(s2, e0, 0);

    /* s1: MP state init + duplicate-edge dedup */
    k_init<<<1024, 256, 0, s1>>>();
    k_clearmap<<<(Ee + 255)/256, 256, 0, s1>>>(edges);
    k_mapbuild<<<(Ee + 255)/256, 256, 0, s1>>>(edges);
    k_isrep<<<(Ee + 255)/256, 256, 0, s1>>>(edges);
    cudaEventRecord(e_s1, s1);

    /* s2: gh GEMM (independent of concat) */
    gemm(s2, st, Hh, whh, Hh, bhh, gh_, Nn, G3, Hh, 0, 1.f, 1.f, 1);
    cudaEventRecord(e_gh, s2);

    /* 0: concat + gi GEMM, then GRU */
    k_concat<<<(Nn*IN_DIM + 255)/256, 256>>>(x, pa);
    gemm(0, inp_, IN_DIM, wih, IN_DIM, bih, gi_, Nn, G3, IN_DIM, 0, 1.f, 1.f, 1);
    cudaStreamWaitEvent(0, e_gh, 0);
    k_gru<<<(Nn*Hh + 255)/256, 256>>>(st, out_h);
    cudaEventRecord(e_gru, 0);

    /* s2: utility MLP (private scratch) */
    cudaStreamWaitEvent(s2, e_gru, 0);
    gemm(s2, h_,  Hh,  uW0, Hh,  ub0, ua_, Nn, 256, Hh,  1, 1.f, 1.f, 1);
    gemm(s2, ua_, 256, uW1, 256, ub1, ub_, Nn, 256, 256, 1, 1.f, 1.f, 1);
    k_gemm16<<<(Nn + BM - 1)/BM, 256, 0, s2>>>(ub_, 256, uW2, 256, ub2, out_u, Nn, 256, 0, 1.f/(float)Nn);
    cudaEventRecord(e_u, s2);

    /* s3: hB GEMM */
    cudaStreamWaitEvent(s3, e_gru, 0);
    gemm(s3, h_, Hh, pW0 + Hh, 2*Hh, pb0, hB_, Nn, Hh, Hh, 0, 1.f, 0.f, 1);
    cudaEventRecord(e_hb, s3);

    /* 0: hA GEMM, then edge0 + p-layers */
    gemm(0, h_, Hh, pW0, 2*Hh, pb0, hA_, Nn, Hh, Hh, 0, 1.f, 0.f, 1);
    cudaStreamWaitEvent(0, e_hb, 0);
    k_edge0<<<(E2*32 + 255)/256, 256>>>(edges, pb0);
    gemm(0, bufA_, Hh,  pW1, Hh,  pb1, bufB_, E2, 256, Hh,  1, 1.f, 1.f, 1);
    gemm(0, bufB_, 256, pW2, 256, pb2, bufA_, E2, 256, 256, 1, 1.f, 1.f, 1);
    k_gemm16<<<(E2 + BM - 1)/BM, 256>>>(bufA_, 256, pW3, 256, pb3, y3_, E2, 256, 1, 1.f);
    k_sum16<<<(Ee*4 + 255)/256, 256>>>();
    /* out_p = d_out + 64001 floats -> NOT 16B aligned: scalar stores */
    gemm(0, z_, 16, pW4, 16, pb4, out_p, Ee, 256, 16, 0, 0.5f/(float)Ee, 2.f, 0);

    /* join u-MLP and MP-state branches before message passing */
    cudaStreamWaitEvent(0, e_u, 0);
    cudaStreamWaitEvent(0, e_s1, 0);

    /* max-sum message passing; qstep(t) pipelined on s2 against msg(t+1) */
    for (int t = 0; t < NITER; t++) {
        int cur = t & 1, nxt = 1 - cur, ab = t & 1;
        k_msg<<<(Ee*32 + 255)/256, 256>>>(edges, out_u, out_p, cur, nxt);
        if (t >= 2) cudaStreamWaitEvent(0, evQ[t-2], 0);   /* aidx[ab] free again */
        k_argmax<<<(Nn*Aa + 255)/256, 256>>>(out_u, nxt, ab);
        cudaEventRecord(evI[t], 0);
        cudaStreamWaitEvent(s2, evI[t], 0);
        k_qstep<<<64, 256, 0, s2>>>(edges, out_u, out_p, ab);
        cudaEventRecord(evQ[t], s2);
    }
    cudaStreamWaitEvent(0, evQ[NITER-1], 0);

    k_final<<<(Nn*Aa + 255)/256, 256>>>(out);
}

// round 6
// speedup vs baseline: 2.5229x; 1.1464x over previous
#include <cuda_runtime.h>
#include <cuda_bf16.h>
#include <math.h>
#include <float.h>

#define Nn   2000
#define Aa   16
#define OBSd 64
#define Hh   128
#define Ee   16000
#define NITER 8
#define IN_DIM 80
#define G3    384
#define E2    (2*Ee)

/* ---------------- scratch (static device globals) ------------------------ */
__device__ __align__(16) float g_inp[Nn*IN_DIM];
__device__ __align__(16) float g_gi[Nn*G3];
__device__ __align__(16) float g_gh[Nn*G3];
__device__ __align__(16) float g_h[Nn*Hh];
__device__ __align__(16) float g_hA[Nn*Hh];
__device__ __align__(16) float g_hB[Nn*Hh];
__device__ __align__(16) float g_ua[Nn*256];
__device__ __align__(16) float g_ub[Nn*256];
__device__ __align__(16) __nv_bfloat16 g_a0h[(size_t)E2*Hh];
__device__ __align__(16) __nv_bfloat16 g_a0l[(size_t)E2*Hh];
__device__ __align__(16) __nv_bfloat16 g_a1h[(size_t)E2*256];
__device__ __align__(16) __nv_bfloat16 g_a1l[(size_t)E2*256];
__device__ __align__(16) __nv_bfloat16 g_a2h[(size_t)E2*256];
__device__ __align__(16) __nv_bfloat16 g_a2l[(size_t)E2*256];
__device__ __align__(16) __nv_bfloat16 g_w1h[256*Hh],  g_w1l[256*Hh];
__device__ __align__(16) __nv_bfloat16 g_w2h[256*256], g_w2l[256*256];
__device__ __align__(16) float g_y3[E2*16];
__device__ __align__(16) float g_z[Ee*16];
__device__ __align__(16) float g_M[Ee*2*Aa];
__device__ __align__(16) float g_S[2*Nn*Aa];
__device__ int   g_map[Nn*Nn];
__device__ int   g_isrep[Ee];
__device__ int   g_aidx[2][Nn];
__device__ int   g_best[Nn];
__device__ float g_part[64];
__device__ int   g_qctr;
__device__ float g_qmax;

/* ---------------- bf16 split helper ---------------------------------------- */
__device__ __forceinline__ void split2(float v0, float v1, unsigned& h, unsigned& l) {
    __nv_bfloat162 hh = __floats2bfloat162_rn(v0, v1);
    float r0 = v0 - __bfloat162float(hh.x);
    float r1 = v1 - __bfloat162float(hh.y);
    __nv_bfloat162 ll = __floats2bfloat162_rn(r0, r1);
    h = *reinterpret_cast<unsigned*>(&hh);
    l = *reinterpret_cast<unsigned*>(&ll);
}

/* ---------------- init ------------------------------------------------------ */
__global__ void k_init() {
    int idx = blockIdx.x*blockDim.x + threadIdx.x;
    int stride = gridDim.x*blockDim.x;
    for (int i = idx; i < Ee*2*Aa; i += stride) g_M[i]   = 0.f;
    for (int i = idx; i < 2*Nn*Aa; i += stride) g_S[i]   = 0.f;
    for (int i = idx; i < Nn; i += stride)      g_best[i] = -1;
    if (idx == 0) { g_qmax = 0.f; g_qctr = 0; }
}

__global__ void k_clearmap(const int* __restrict__ edges) {
    int e = blockIdx.x*blockDim.x + threadIdx.x;
    if (e >= Ee) return;
    g_map[edges[2*e]*Nn + edges[2*e+1]] = 0x7fffffff;
}

__global__ void k_mapbuild(const int* __restrict__ edges) {
    int e = blockIdx.x*blockDim.x + threadIdx.x;
    if (e >= Ee) return;
    atomicMin(&g_map[edges[2*e]*Nn + edges[2*e+1]], e);
}

__global__ void k_isrep(const int* __restrict__ edges) {
    int e = blockIdx.x*blockDim.x + threadIdx.x;
    if (e >= Ee) return;
    g_isrep[e] = (g_map[edges[2*e]*Nn + edges[2*e+1]] == e) ? 1 : 0;
}

/* ---------------- weight split --------------------------------------------- */
__global__ void k_wsplit(const float* __restrict__ W, int n,
                         __nv_bfloat16* __restrict__ Wh, __nv_bfloat16* __restrict__ Wl) {
    int i = blockIdx.x*blockDim.x + threadIdx.x;
    if (i >= n) return;
    float v = W[i];
    __nv_bfloat16 h = __float2bfloat16(v);
    Wh[i] = h;
    Wl[i] = __float2bfloat16(v - __bfloat162float(h));
}

/* ---------------- encoder input concat ------------------------------------- */
__global__ void k_concat(const float* __restrict__ x, const float* __restrict__ pa) {
    int idx = blockIdx.x*blockDim.x + threadIdx.x;
    if (idx >= Nn*IN_DIM) return;
    int n = idx / IN_DIM, c = idx % IN_DIM;
    g_inp[idx] = (c < OBSd) ? x[n*OBSd + c] : pa[n*Aa + (c - OBSd)];
}

/* ---------------- 128x128x8 double-buffered SGEMM (fp32) ------------------- */
#define BM 128
#define BN 128
#define BK 8

__global__ __launch_bounds__(256,2)
void k_gemm128(const float* __restrict__ X, int lda,
               const float* __restrict__ W, int ldw,
               const float* __restrict__ bias, float* __restrict__ C,
               int M, int N, int K, int relu, float scale, float bias_mult,
               int vec_store)
{
    __shared__ __align__(16) float As[2][BK][BM+4];
    __shared__ __align__(16) float Bs[2][BK][BN+4];
    const int t   = threadIdx.x;
    const int bm  = blockIdx.y * BM;
    const int bn  = blockIdx.x * BN;
    const int lrow = t >> 1;
    const int lcol = (t & 1) << 2;
    const int tx = t & 15, ty = t >> 4;
    const int cx0 = tx << 2, cx1 = 64 + (tx << 2);
    const int ry0 = ty << 2, ry1 = 64 + (ty << 2);

    float acc[8][8];
#pragma unroll
    for (int i = 0; i < 8; i++)
#pragma unroll
        for (int j = 0; j < 8; j++) acc[i][j] = 0.f;

    const bool xok = (bm + lrow) < M;
    const bool wok = (bn + lrow) < N;
    const float* Xp = X + (size_t)(bm + lrow)*lda + lcol;
    const float* Wp = W + (size_t)(bn + lrow)*ldw + lcol;
    const float4 z4 = make_float4(0.f,0.f,0.f,0.f);

    float4 xa = xok ? *reinterpret_cast<const float4*>(Xp) : z4;
    float4 wa = wok ? *reinterpret_cast<const float4*>(Wp) : z4;
    As[0][lcol+0][lrow]=xa.x; As[0][lcol+1][lrow]=xa.y; As[0][lcol+2][lrow]=xa.z; As[0][lcol+3][lrow]=xa.w;
    Bs[0][lcol+0][lrow]=wa.x; Bs[0][lcol+1][lrow]=wa.y; Bs[0][lcol+2][lrow]=wa.z; Bs[0][lcol+3][lrow]=wa.w;
    __syncthreads();

    int buf = 0;
    for (int k0 = 0; k0 < K; k0 += BK) {
        const bool more = (k0 + BK) < K;
        float4 xn = z4, wn = z4;
        if (more) {
            if (xok) xn = *reinterpret_cast<const float4*>(Xp + k0 + BK);
            if (wok) wn = *reinterpret_cast<const float4*>(Wp + k0 + BK);
        }
#pragma unroll
        for (int k = 0; k < BK; k++) {
            float4 a0 = *reinterpret_cast<const float4*>(&As[buf][k][ry0]);
            float4 a1 = *reinterpret_cast<const float4*>(&As[buf][k][ry1]);
            float4 b0 = *reinterpret_cast<const float4*>(&Bs[buf][k][cx0]);
            float4 b1 = *reinterpret_cast<const float4*>(&Bs[buf][k][cx1]);
            float ar[8] = {a0.x,a0.y,a0.z,a0.w,a1.x,a1.y,a1.z,a1.w};
            float br[8] = {b0.x,b0.y,b0.z,b0.w,b1.x,b1.y,b1.z,b1.w};
#pragma unroll
            for (int i = 0; i < 8; i++)
#pragma unroll
                for (int j = 0; j < 8; j++)
                    acc[i][j] = fmaf(ar[i], br[j], acc[i][j]);
        }
        if (more) {
            int nb = buf ^ 1;
            As[nb][lcol+0][lrow]=xn.x; As[nb][lcol+1][lrow]=xn.y; As[nb][lcol+2][lrow]=xn.z; As[nb][lcol+3][lrow]=xn.w;
            Bs[nb][lcol+0][lrow]=wn.x; Bs[nb][lcol+1][lrow]=wn.y; Bs[nb][lcol+2][lrow]=wn.z; Bs[nb][lcol+3][lrow]=wn.w;
            __syncthreads();
            buf = nb;
        }
    }

    float4 bv0 = *reinterpret_cast<const float4*>(&bias[bn + cx0]);
    float4 bv1 = *reinterpret_cast<const float4*>(&bias[bn + cx1]);
#pragma unroll
    for (int ii = 0; ii < 8; ii++) {
        int r = bm + ((ii < 4) ? (ry0 + ii) : (ry1 + ii - 4));
        if (r >= M) continue;
        float o[8];
        o[0]=acc[ii][0]+bias_mult*bv0.x; o[1]=acc[ii][1]+bias_mult*bv0.y;
        o[2]=acc[ii][2]+bias_mult*bv0.z; o[3]=acc[ii][3]+bias_mult*bv0.w;
        o[4]=acc[ii][4]+bias_mult*bv1.x; o[5]=acc[ii][5]+bias_mult*bv1.y;
        o[6]=acc[ii][6]+bias_mult*bv1.z; o[7]=acc[ii][7]+bias_mult*bv1.w;
        if (relu) {
#pragma unroll
            for (int j = 0; j < 8; j++) o[j] = fmaxf(o[j], 0.f);
        }
#pragma unroll
        for (int j = 0; j < 8; j++) o[j] *= scale;
        if (vec_store) {
            *reinterpret_cast<float4*>(&C[(size_t)r*N + bn + cx0]) = make_float4(o[0],o[1],o[2],o[3]);
            *reinterpret_cast<float4*>(&C[(size_t)r*N + bn + cx1]) = make_float4(o[4],o[5],o[6],o[7]);
        } else {
            float* c0 = &C[(size_t)r*N + bn + cx0];
            float* c1 = &C[(size_t)r*N + bn + cx1];
            c0[0]=o[0]; c0[1]=o[1]; c0[2]=o[2]; c0[3]=o[3];
            c1[0]=o[4]; c1[1]=o[5]; c1[2]=o[6]; c1[3]=o[7];
        }
    }
}

/* ---------------- split-bf16 tensor GEMM (mma.sync m16n8k16) --------------- */
/* C = relu(Ahi@(Bh+Bl)^T + Alo@Bh^T + bias), output split bf16 hi/lo.        */
/* Requires M%128==0, N%64==0, K%32==0. A [M,K] bf16 hi/lo, B(weights) [N,K]. */
#define TBM 128
#define TBN 64
#define TBK 32

#define MMA_BF16(c, a, b) \
    asm volatile("mma.sync.aligned.m16n8k16.row.col.f32.bf16.bf16.f32 " \
        "{%0,%1,%2,%3}, {%4,%5,%6,%7}, {%8,%9}, {%0,%1,%2,%3};" \
        : "+f"((c)[0]), "+f"((c)[1]), "+f"((c)[2]), "+f"((c)[3]) \
        : "r"((a)[0]), "r"((a)[1]), "r"((a)[2]), "r"((a)[3]), "r"((b)[0]), "r"((b)[1]))

__device__ __forceinline__ unsigned lds_bf2(const __nv_bfloat16* p) {
    return *reinterpret_cast<const unsigned*>(p);
}

__global__ __launch_bounds__(256,2)
void k_tgemm(const __nv_bfloat16* __restrict__ Ah, const __nv_bfloat16* __restrict__ Al,
             const __nv_bfloat16* __restrict__ Bh, const __nv_bfloat16* __restrict__ Bl,
             const float* __restrict__ bias, int M, int N, int K,
             __nv_bfloat16* __restrict__ Ch, __nv_bfloat16* __restrict__ Cl)
{
    __shared__ __align__(16) __nv_bfloat16 sAh[TBM][TBK+8];
    __shared__ __align__(16) __nv_bfloat16 sAl[TBM][TBK+8];
    __shared__ __align__(16) __nv_bfloat16 sBh[TBN][TBK+8];
    __shared__ __align__(16) __nv_bfloat16 sBl[TBN][TBK+8];

    const int t = threadIdx.x;
    const int bm = blockIdx.y * TBM;
    const int bn = blockIdx.x * TBN;
    const int wid = t >> 5;
    const int lane = t & 31;
    const int g  = lane >> 2;
    const int tg = lane & 3;
    const int warp_m = (wid & 3) * 32;
    const int warp_n = (wid >> 2) * 32;

    float c[2][4][4];
#pragma unroll
    for (int mi = 0; mi < 2; mi++)
#pragma unroll
        for (int ni = 0; ni < 4; ni++)
#pragma unroll
            for (int q = 0; q < 4; q++) c[mi][ni][q] = 0.f;

    /* loader indices */
    const int ar = t >> 1;                 /* A row 0..127 */
    const int ac = (t & 1) * 16;           /* A elem offset 0 or 16 */
    const int br = t >> 2;                 /* B row 0..63 */
    const int bc = (t & 3) * 8;            /* B elem offset */

    for (int kk = 0; kk < K; kk += TBK) {
        /* load A tile: 128 x 32 bf16 per array */
        {
            uint4 vh0 = *reinterpret_cast<const uint4*>(Ah + (size_t)(bm+ar)*K + kk + ac);
            uint4 vh1 = *reinterpret_cast<const uint4*>(Ah + (size_t)(bm+ar)*K + kk + ac + 8);
            uint4 vl0 = *reinterpret_cast<const uint4*>(Al + (size_t)(bm+ar)*K + kk + ac);
            uint4 vl1 = *reinterpret_cast<const uint4*>(Al + (size_t)(bm+ar)*K + kk + ac + 8);
            *reinterpret_cast<uint4*>(&sAh[ar][ac])     = vh0;
            *reinterpret_cast<uint4*>(&sAh[ar][ac + 8]) = vh1;
            *reinterpret_cast<uint4*>(&sAl[ar][ac])     = vl0;
            *reinterpret_cast<uint4*>(&sAl[ar][ac + 8]) = vl1;
        }
        /* load B tile: 64 x 32 bf16 per array */
        if (t < 256) {
            uint4 wh = *reinterpret_cast<const uint4*>(Bh + (size_t)(bn+br)*K + kk + bc);
            uint4 wl = *reinterpret_cast<const uint4*>(Bl + (size_t)(bn+br)*K + kk + bc);
            *reinterpret_cast<uint4*>(&sBh[br][bc]) = wh;
            *reinterpret_cast<uint4*>(&sBl[br][bc]) = wl;
        }
        __syncthreads();

#pragma unroll
        for (int k16 = 0; k16 < TBK; k16 += 16) {
            unsigned ah[2][4], al[2][4], bh[4][2], bl[4][2];
#pragma unroll
            for (int mi = 0; mi < 2; mi++) {
                int rb = warp_m + mi*16;
                ah[mi][0] = lds_bf2(&sAh[rb+g  ][k16 + 2*tg]);
                ah[mi][1] = lds_bf2(&sAh[rb+g+8][k16 + 2*tg]);
                ah[mi][2] = lds_bf2(&sAh[rb+g  ][k16 + 2*tg + 8]);
                ah[mi][3] = lds_bf2(&sAh[rb+g+8][k16 + 2*tg + 8]);
                al[mi][0] = lds_bf2(&sAl[rb+g  ][k16 + 2*tg]);
                al[mi][1] = lds_bf2(&sAl[rb+g+8][k16 + 2*tg]);
                al[mi][2] = lds_bf2(&sAl[rb+g  ][k16 + 2*tg + 8]);
                al[mi][3] = lds_bf2(&sAl[rb+g+8][k16 + 2*tg + 8]);
            }
#pragma unroll
            for (int ni = 0; ni < 4; ni++) {
                int cb = warp_n + ni*8;
                bh[ni][0] = lds_bf2(&sBh[cb+g][k16 + 2*tg]);
                bh[ni][1] = lds_bf2(&sBh[cb+g][k16 + 2*tg + 8]);
                bl[ni][0] = lds_bf2(&sBl[cb+g][k16 + 2*tg]);
                bl[ni][1] = lds_bf2(&sBl[cb+g][k16 + 2*tg + 8]);
            }
#pragma unroll
            for (int mi = 0; mi < 2; mi++)
#pragma unroll
                for (int ni = 0; ni < 4; ni++) {
                    MMA_BF16(c[mi][ni], ah[mi], bh[ni]);
                    MMA_BF16(c[mi][ni], ah[mi], bl[ni]);
                    MMA_BF16(c[mi][ni], al[mi], bh[ni]);
                }
        }
        __syncthreads();
    }

    /* epilogue: bias + relu + split-store bf16 hi/lo */
#pragma unroll
    for (int mi = 0; mi < 2; mi++) {
        int r0 = bm + warp_m + mi*16 + g;
        int r1 = r0 + 8;
#pragma unroll
        for (int ni = 0; ni < 4; ni++) {
            int cb = bn + warp_n + ni*8 + 2*tg;
            float b0 = bias[cb], b1 = bias[cb+1];
            float v0 = fmaxf(c[mi][ni][0] + b0, 0.f);
            float v1 = fmaxf(c[mi][ni][1] + b1, 0.f);
            float v2 = fmaxf(c[mi][ni][2] + b0, 0.f);
            float v3 = fmaxf(c[mi][ni][3] + b1, 0.f);
            unsigned h01, l01, h23, l23;
            split2(v0, v1, h01, l01);
            split2(v2, v3, h23, l23);
            *reinterpret_cast<unsigned*>(&Ch[(size_t)r0*N + cb]) = h01;
            *reinterpret_cast<unsigned*>(&Cl[(size_t)r0*N + cb]) = l01;
            *reinterpret_cast<unsigned*>(&Ch[(size_t)r1*N + cb]) = h23;
            *reinterpret_cast<unsigned*>(&Cl[(size_t)r1*N + cb]) = l23;
        }
    }
}

/* ---------------- skinny GEMM, N=16, fp32 input ---------------------------- */
__global__ __launch_bounds__(256,4)
void k_gemm16(const float* __restrict__ X, int lda,
              const float* __restrict__ W, int ldw,
              const float* __restrict__ bias, float* __restrict__ C,
              int M, int K, int relu, float scale)
{
    __shared__ __align__(16) float As[16][BM+4];
    __shared__ float Bs[16][17];
    const int t = threadIdx.x;
    const int bm = blockIdx.x * BM;
    const int arow = t >> 1, acol = (t & 1) << 3;
    const int tx = t & 15, ty = t >> 4;
    const bool xok = (bm + arow) < M;
    const float4 z4 = make_float4(0.f,0.f,0.f,0.f);

    float acc[8];
#pragma unroll
    for (int i = 0; i < 8; i++) acc[i] = 0.f;

    for (int k0 = 0; k0 < K; k0 += 16) {
        float4 v0 = z4, v1 = z4;
        if (xok) {
            v0 = *reinterpret_cast<const float4*>(X + (size_t)(bm+arow)*lda + k0 + acol);
            v1 = *reinterpret_cast<const float4*>(X + (size_t)(bm+arow)*lda + k0 + acol + 4);
        }
        float4 wv = z4;
        int wr = t >> 2, wc = (t & 3) << 2;
        if (t < 64) wv = *reinterpret_cast<const float4*>(W + (size_t)wr*ldw + k0 + wc);
        __syncthreads();
        As[acol+0][arow]=v0.x; As[acol+1][arow]=v0.y; As[acol+2][arow]=v0.z; As[acol+3][arow]=v0.w;
        As[acol+4][arow]=v1.x; As[acol+5][arow]=v1.y; As[acol+6][arow]=v1.z; As[acol+7][arow]=v1.w;
        if (t < 64) { Bs[wc+0][wr]=wv.x; Bs[wc+1][wr]=wv.y; Bs[wc+2][wr]=wv.z; Bs[wc+3][wr]=wv.w; }
        __syncthreads();
#pragma unroll
        for (int k = 0; k < 16; k++) {
            float b = Bs[k][tx];
            float4 a0 = *reinterpret_cast<const float4*>(&As[k][ty*8]);
            float4 a1 = *reinterpret_cast<const float4*>(&As[k][ty*8+4]);
            acc[0]=fmaf(a0.x,b,acc[0]); acc[1]=fmaf(a0.y,b,acc[1]);
            acc[2]=fmaf(a0.z,b,acc[2]); acc[3]=fmaf(a0.w,b,acc[3]);
            acc[4]=fmaf(a1.x,b,acc[4]); acc[5]=fmaf(a1.y,b,acc[5]);
            acc[6]=fmaf(a1.z,b,acc[6]); acc[7]=fmaf(a1.w,b,acc[7]);
        }
        __syncthreads();
    }
    float bb = bias[tx];
#pragma unroll
    for (int i = 0; i < 8; i++) {
        int r = bm + ty*8 + i;
        if (r >= M) continue;
        float v = acc[i] + bb;
        if (relu) v = fmaxf(v, 0.f);
        C[(size_t)r*16 + tx] = v * scale;
    }
}

/* ---------------- skinny GEMM, N=16, split-bf16 input ---------------------- */
__global__ __launch_bounds__(256,4)
void k_gemm16b(const __nv_bfloat16* __restrict__ Xh, const __nv_bfloat16* __restrict__ Xl, int lda,
               const float* __restrict__ W, int ldw,
               const float* __restrict__ bias, float* __restrict__ C,
               int M, int K, int relu, float scale)
{
    __shared__ __align__(16) float As[16][BM+4];
    __shared__ float Bs[16][17];
    const int t = threadIdx.x;
    const int bm = blockIdx.x * BM;
    const int arow = t >> 1, acol = (t & 1) << 3;
    const int tx = t & 15, ty = t >> 4;

    float acc[8];
#pragma unroll
    for (int i = 0; i < 8; i++) acc[i] = 0.f;

    for (int k0 = 0; k0 < K; k0 += 16) {
        uint4 uh = *reinterpret_cast<const uint4*>(Xh + (size_t)(bm+arow)*lda + k0 + acol);
        uint4 ul = *reinterpret_cast<const uint4*>(Xl + (size_t)(bm+arow)*lda + k0 + acol);
        float4 wv = make_float4(0.f,0.f,0.f,0.f);
        int wr = t >> 2, wc = (t & 3) << 2;
        if (t < 64) wv = *reinterpret_cast<const float4*>(W + (size_t)wr*ldw + k0 + wc);
        __syncthreads();
        {
            const unsigned* ph = reinterpret_cast<const unsigned*>(&uh);
            const unsigned* pl = reinterpret_cast<const unsigned*>(&ul);
#pragma unroll
            for (int q = 0; q < 4; q++) {
                __nv_bfloat162 hh = *reinterpret_cast<const __nv_bfloat162*>(&ph[q]);
                __nv_bfloat162 ll = *reinterpret_cast<const __nv_bfloat162*>(&pl[q]);
                float2 fh = __bfloat1622float2(hh);
                float2 fl = __bfloat1622float2(ll);
                As[acol + 2*q    ][arow] = fh.x + fl.x;
                As[acol + 2*q + 1][arow] = fh.y + fl.y;
            }
        }
        if (t < 64) { Bs[wc+0][wr]=wv.x; Bs[wc+1][wr]=wv.y; Bs[wc+2][wr]=wv.z; Bs[wc+3][wr]=wv.w; }
        __syncthreads();
#pragma unroll
        for (int k = 0; k < 16; k++) {
            float b = Bs[k][tx];
            float4 a0 = *reinterpret_cast<const float4*>(&As[k][ty*8]);
            float4 a1 = *reinterpret_cast<const float4*>(&As[k][ty*8+4]);
            acc[0]=fmaf(a0.x,b,acc[0]); acc[1]=fmaf(a0.y,b,acc[1]);
            acc[2]=fmaf(a0.z,b,acc[2]); acc[3]=fmaf(a0.w,b,acc[3]);
            acc[4]=fmaf(a1.x,b,acc[4]); acc[5]=fmaf(a1.y,b,acc[5]);
            acc[6]=fmaf(a1.z,b,acc[6]); acc[7]=fmaf(a1.w,b,acc[7]);
        }
        __syncthreads();
    }
    float bb = bias[tx];
#pragma unroll
    for (int i = 0; i < 8; i++) {
        int r = bm + ty*8 + i;
        float v = acc[i] + bb;
        if (relu) v = fmaxf(v, 0.f);
        C[(size_t)r*16 + tx] = v * scale;
    }
}

/* ---------------- GRU elementwise ------------------------------------------ */
__global__ void k_gru(const float* __restrict__ hprev, float* __restrict__ out_h) {
    int idx = blockIdx.x*blockDim.x + threadIdx.x;
    if (idx >= Nn*Hh) return;
    int n = idx / Hh, d = idx % Hh;
    const float* gi = g_gi + n*G3;
    const float* gh = g_gh + n*G3;
    float r = 1.f/(1.f + expf(-(gi[d]       + gh[d])));
    float z = 1.f/(1.f + expf(-(gi[Hh+d]    + gh[Hh+d])));
    float t = tanhf(gi[2*Hh+d] + r*gh[2*Hh+d]);
    float h = (1.f - z)*t + z*hprev[idx];
    g_h[idx] = h;
    out_h[idx] = h;
}

/* ---------------- p-layer0: relu(hA[a]+hB[b]+b0) -> split bf16 ------------- */
__global__ void k_edge0(const int* __restrict__ edges, const float* __restrict__ b0) {
    int idx = blockIdx.x*blockDim.x + threadIdx.x;
    if (idx >= E2*32) return;
    int r = idx >> 5;
    int c = (idx & 31) << 2;
    int e = (r < Ee) ? r : r - Ee;
    int i = edges[2*e], j = edges[2*e+1];
    int na = (r < Ee) ? i : j;
    int nb = (r < Ee) ? j : i;
    float4 a = *reinterpret_cast<const float4*>(&g_hA[na*Hh + c]);
    float4 b = *reinterpret_cast<const float4*>(&g_hB[nb*Hh + c]);
    float4 bb = *reinterpret_cast<const float4*>(&b0[c]);
    float v0 = fmaxf(a.x + b.x + bb.x, 0.f);
    float v1 = fmaxf(a.y + b.y + bb.y, 0.f);
    float v2 = fmaxf(a.z + b.z + bb.z, 0.f);
    float v3 = fmaxf(a.w + b.w + bb.w, 0.f);
    unsigned h01, l01, h23, l23;
    split2(v0, v1, h01, l01);
    split2(v2, v3, h23, l23);
    size_t base = (size_t)r*Hh + c;
    *reinterpret_cast<unsigned*>(&g_a0h[base])     = h01;
    *reinterpret_cast<unsigned*>(&g_a0h[base + 2]) = h23;
    *reinterpret_cast<unsigned*>(&g_a0l[base])     = l01;
    *reinterpret_cast<unsigned*>(&g_a0l[base + 2]) = l23;
}

/* ---------------- z = y3_ij + y3_ji ----------------------------------------- */
__global__ void k_sum16() {
    int idx = blockIdx.x*blockDim.x + threadIdx.x;
    if (idx >= Ee*4) return;
    int e = idx >> 2, c = (idx & 3) << 2;
    float4 a = *reinterpret_cast<const float4*>(&g_y3[e*16 + c]);
    float4 b = *reinterpret_cast<const float4*>(&g_y3[(size_t)(Ee + e)*16 + c]);
    *reinterpret_cast<float4*>(&g_z[e*16 + c]) = make_float4(a.x+b.x, a.y+b.y, a.z+b.z, a.w+b.w);
}

/* ---------------- message update + fused scatter (rep edges only) ---------- */
__global__ void k_msg(const int* __restrict__ edges, const float* __restrict__ u,
                      const float* __restrict__ p, int cur, int nxt) {
    int w = (blockIdx.x*blockDim.x + threadIdx.x) >> 5;
    if (w >= Ee) return;
    if (!g_isrep[w]) return;
    int lane = threadIdx.x & 31;
    int b = lane & 15;
    const float* S  = g_S + cur*Nn*Aa;
    float*       Sn = g_S + nxt*Nn*Aa;
    int i = edges[2*w], j = edges[2*w+1];
    float Mi = g_M[(w*2 + 0)*Aa + b];
    float Mj = g_M[(w*2 + 1)*Aa + b];
    float base_i = u[i*Aa + b] + S[i*Aa + b] - Mi;
    float base_j = u[j*Aa + b] + S[j*Aa + b] - Mj;
    const float* pe = p + (size_t)w*256;
    float mtj = -FLT_MAX, colmax = -FLT_MAX;
#pragma unroll
    for (int a2 = 0; a2 < 16; a2++) {
        float pab = pe[a2*16 + b];
        float bia = __shfl_sync(0xffffffffu, base_i, a2, 16);
        mtj    = fmaxf(mtj, pab + bia);
        colmax = fmaxf(colmax, pab);
    }
    float mti = colmax + base_j;
    float s1 = mtj, s2 = mti;
#pragma unroll
    for (int m = 8; m; m >>= 1) {
        s1 += __shfl_xor_sync(0xffffffffu, s1, m, 16);
        s2 += __shfl_xor_sync(0xffffffffu, s2, m, 16);
    }
    mtj -= s1 * (1.f/16.f);
    mti -= s2 * (1.f/16.f);
    if (lane < 16) {
        g_M[(w*2 + 1)*Aa + b] = mtj;
        g_M[(w*2 + 0)*Aa + b] = mti;
        atomicAdd(&Sn[i*Aa + b], mti);
        atomicAdd(&Sn[j*Aa + b], mtj);
    }
}

/* ---------------- per-node argmax + zero other S buffer -------------------- */
__global__ void k_argmax(const float* __restrict__ u, int nxt, int ab) {
    int idx = blockIdx.x*blockDim.x + threadIdx.x;
    const float* S = g_S + nxt*Nn*Aa;
    float* Sz = g_S + (1 - nxt)*Nn*Aa;
    if (idx < Nn) {
        float best = -FLT_MAX; int bi = 0;
#pragma unroll
        for (int a = 0; a < Aa; a++) {
            float v = u[idx*Aa + a] + S[idx*Aa + a];
            if (v > best) { best = v; bi = a; }
        }
        g_aidx[ab][idx] = bi;
    }
    if (idx < Nn*Aa) Sz[idx] = 0.f;
}

/* ---------------- q partial sums + fused last-block final reduce ----------- */
__global__ void k_qstep(const int* __restrict__ edges, const float* __restrict__ u,
                        const float* __restrict__ p, int ab) {
    __shared__ float red[256];
    __shared__ int lastdone;
    const int* aidx = g_aidx[ab];
    int tid = threadIdx.x, bid = blockIdx.x;
    int gt = bid*256 + tid;
    float local = 0.f;
    for (int n = gt; n < Nn; n += 64*256) local += u[n*Aa + aidx[n]];
    for (int e = gt; e < Ee; e += 64*256) {
        int i = edges[2*e], j = edges[2*e+1];
        local += p[(size_t)e*256 + aidx[i]*Aa + aidx[j]];
    }
    red[tid] = local;
    __syncthreads();
    for (int s = 128; s > 0; s >>= 1) {
        if (tid < s) red[tid] += red[tid + s];
        __syncthreads();
    }
    if (tid == 0) {
        g_part[bid] = red[0];
        __threadfence();
        int done = atomicAdd(&g_qctr, 1);
        lastdone = (done == 63) ? 1 : 0;
    }
    __syncthreads();
    if (!lastdone) return;
    __shared__ int better;
    if (tid == 0) {
        float q = 0.f;
        for (int k = 0; k < 64; k++) q += g_part[k];
        if (q > g_qmax) { g_qmax = q; better = 1; } else better = 0;
        g_qctr = 0;
    }
    __syncthreads();
    if (better) {
        for (int n = tid; n < Nn; n += 256) g_best[n] = g_aidx[ab][n];
    }
}

/* ---------------- finalize --------------------------------------------------- */
__global__ void k_final(float* __restrict__ out) {
    int idx = blockIdx.x*blockDim.x + threadIdx.x;
    if (idx >= Nn*Aa) return;
    int n = idx >> 4, a = idx & 15;
    out[idx] = (g_best[n] == a) ? 1.f : 0.f;
    if (idx == 0) out[Nn*Aa] = g_qmax;
}

/* ---------------- host ------------------------------------------------------- */
static inline void gemm(cudaStream_t st, const float* X, int lda, const float* W, int ldw,
                        const float* b, float* C, int M, int N, int K,
                        int relu, float scale, float bias_mult, int vec_store) {
    dim3 grid(N/BN, (M + BM - 1)/BM);
    k_gemm128<<<grid, 256, 0, st>>>(X, lda, W, ldw, b, C, M, N, K, relu, scale, bias_mult, vec_store);
}

extern "C" void kernel_launch(void* const* d_in, const int* in_sizes, int n_in,
                              void* d_out, int out_size) {
    const float* x    = (const float*)d_in[0];
    const float* pa   = (const float*)d_in[1];
    const float* st   = (const float*)d_in[2];
    const int*   edges= (const int*)  d_in[3];
    const float* wih  = (const float*)d_in[4];
    const float* whh  = (const float*)d_in[5];
    const float* bih  = (const float*)d_in[6];
    const float* bhh  = (const float*)d_in[7];
    const float* uW0  = (const float*)d_in[8];   const float* ub0 = (const float*)d_in[9];
    const float* uW1  = (const float*)d_in[10];  const float* ub1 = (const float*)d_in[11];
    const float* uW2  = (const float*)d_in[12];  const float* ub2 = (const float*)d_in[13];
    const float* pW0  = (const float*)d_in[14];  const float* pb0 = (const float*)d_in[15];
    const float* pW1  = (const float*)d_in[16];  const float* pb1 = (const float*)d_in[17];
    const float* pW2  = (const float*)d_in[18];  const float* pb2 = (const float*)d_in[19];
    const float* pW3  = (const float*)d_in[20];  const float* pb3 = (const float*)d_in[21];
    const float* pW4  = (const float*)d_in[22];  const float* pb4 = (const float*)d_in[23];

    float* out   = (float*)d_out;
    float* out_u = out + Nn*Aa + 1;
    float* out_p = out_u + Nn*Aa;
    float* out_h = out_p + (size_t)Ee*Aa*Aa;

    float *inp_, *gi_, *gh_, *h_, *hA_, *hB_, *ua_, *ub_, *y3_, *z_;
    __nv_bfloat16 *a0h_, *a0l_, *a1h_, *a1l_, *a2h_, *a2l_, *w1h_, *w1l_, *w2h_, *w2l_;
    cudaGetSymbolAddress((void**)&inp_,  g_inp);
    cudaGetSymbolAddress((void**)&gi_,   g_gi);
    cudaGetSymbolAddress((void**)&gh_,   g_gh);
    cudaGetSymbolAddress((void**)&h_,    g_h);
    cudaGetSymbolAddress((void**)&hA_,   g_hA);
    cudaGetSymbolAddress((void**)&hB_,   g_hB);
    cudaGetSymbolAddress((void**)&ua_,   g_ua);
    cudaGetSymbolAddress((void**)&ub_,   g_ub);
    cudaGetSymbolAddress((void**)&y3_,   g_y3);
    cudaGetSymbolAddress((void**)&z_,    g_z);
    cudaGetSymbolAddress((void**)&a0h_,  g_a0h);
    cudaGetSymbolAddress((void**)&a0l_,  g_a0l);
    cudaGetSymbolAddress((void**)&a1h_,  g_a1h);
    cudaGetSymbolAddress((void**)&a1l_,  g_a1l);
    cudaGetSymbolAddress((void**)&a2h_,  g_a2h);
    cudaGetSymbolAddress((void**)&a2l_,  g_a2l);
    cudaGetSymbolAddress((void**)&w1h_,  g_w1h);
    cudaGetSymbolAddress((void**)&w1l_,  g_w1l);
    cudaGetSymbolAddress((void**)&w2h_,  g_w2h);
    cudaGetSymbolAddress((void**)&w2l_,  g_w2l);

    static cudaStream_t s1 = 0, s2 = 0, s3 = 0;
    static cudaEvent_t e0 = 0, e_gh, e_gru, e_u, e_hb, e_s1, e_w, evI[NITER], evQ[NITER];
    if (!e0) {
        cudaStreamCreateWithFlags(&s1, cudaStreamNonBlocking);
        cudaStreamCreateWithFlags(&s2, cudaStreamNonBlocking);
        cudaStreamCreateWithFlags(&s3, cudaStreamNonBlocking);
        cudaEventCreateWithFlags(&e0,   cudaEventDisableTiming);
        cudaEventCreateWithFlags(&e_gh, cudaEventDisableTiming);
        cudaEventCreateWithFlags(&e_gru,cudaEventDisableTiming);
        cudaEventCreateWithFlags(&e_u,  cudaEventDisableTiming);
        cudaEventCreateWithFlags(&e_hb, cudaEventDisableTiming);
        cudaEventCreateWithFlags(&e_s1, cudaEventDisableTiming);
        cudaEventCreateWithFlags(&e_w,  cudaEventDisableTiming);
        for (int t = 0; t < NITER; t++) {
            cudaEventCreateWithFlags(&evI[t], cudaEventDisableTiming);
            cudaEventCreateWithFlags(&evQ[t], cudaEventDisableTiming);
        }
    }

    /* fork */
    cudaEventRecord(e0, 0);
    cudaStreamWaitEvent(s1, e0, 0);
    cudaStreamWaitEvent(s2, e0, 0);
    cudaStreamWaitEvent(s3, e0, 0);

    /* s1: MP state init + duplicate-edge dedup */
    k_init<<<1024, 256, 0, s1>>>();
    k_clearmap<<<(Ee + 255)/256, 256, 0, s1>>>(edges);
    k_mapbuild<<<(Ee + 255)/256, 256, 0, s1>>>(edges);
    k_isrep<<<(Ee + 255)/256, 256, 0, s1>>>(edges);
    cudaEventRecord(e_s1, s1);

    /* s3: weight splits (input-only deps) */
    k_wsplit<<<(256*Hh + 255)/256, 256, 0, s3>>>(pW1, 256*Hh, w1h_, w1l_);
    k_wsplit<<<(256*256 + 255)/256, 256, 0, s3>>>(pW2, 256*256, w2h_, w2l_);
    cudaEventRecord(e_w, s3);

    /* s2: gh GEMM */
    gemm(s2, st, Hh, whh, Hh, bhh, gh_, Nn, G3, Hh, 0, 1.f, 1.f, 1);
    cudaEventRecord(e_gh, s2);

    /* 0: concat + gi GEMM, then GRU */
    k_concat<<<(Nn*IN_DIM + 255)/256, 256>>>(x, pa);
    gemm(0, inp_, IN_DIM, wih, IN_DIM, bih, gi_, Nn, G3, IN_DIM, 0, 1.f, 1.f, 1);
    cudaStreamWaitEvent(0, e_gh, 0);
    k_gru<<<(Nn*Hh + 255)/256, 256>>>(st, out_h);
    cudaEventRecord(e_gru, 0);

    /* s2: utility MLP */
    cudaStreamWaitEvent(s2, e_gru, 0);
    gemm(s2, h_,  Hh,  uW0, Hh,  ub0, ua_, Nn, 256, Hh,  1, 1.f, 1.f, 1);
    gemm(s2, ua_, 256, uW1, 256, ub1, ub_, Nn, 256, 256, 1, 1.f, 1.f, 1);
    k_gemm16<<<(Nn + BM - 1)/BM, 256, 0, s2>>>(ub_, 256, uW2, 256, ub2, out_u, Nn, 256, 0, 1.f/(float)Nn);
    cudaEventRecord(e_u, s2);

    /* s3: hB GEMM */
    cudaStreamWaitEvent(s3, e_gru, 0);
    gemm(s3, h_, Hh, pW0 + Hh, 2*Hh, pb0, hB_, Nn, Hh, Hh, 0, 1.f, 0.f, 1);
    cudaEventRecord(e_hb, s3);

    /* 0: hA GEMM, edge0 (split), tensor layers 1-2, layer3, merge, layer4 */
    gemm(0, h_, Hh, pW0, 2*Hh, pb0, hA_, Nn, Hh, Hh, 0, 1.f, 0.f, 1);
    cudaStreamWaitEvent(0, e_hb, 0);
    k_edge0<<<(E2*32 + 255)/256, 256>>>(edges, pb0);
    cudaStreamWaitEvent(0, e_w, 0);
    {
        dim3 g1(256/TBN, E2/TBM);
        k_tgemm<<<g1, 256>>>(a0h_, a0l_, w1h_, w1l_, pb1, E2, 256, Hh,  a1h_, a1l_);
        k_tgemm<<<g1, 256>>>(a1h_, a1l_, w2h_, w2l_, pb2, E2, 256, 256, a2h_, a2l_);
    }
    k_gemm16b<<<E2/BM, 256>>>(a2h_, a2l_, 256, pW3, 256, pb3, y3_, E2, 256, 1, 1.f);
    k_sum16<<<(Ee*4 + 255)/256, 256>>>();
    /* out_p = d_out + 64001 floats -> NOT 16B aligned: scalar stores */
    gemm(0, z_, 16, pW4, 16, pb4, out_p, Ee, 256, 16, 0, 0.5f/(float)Ee, 2.f, 0);

    /* join */
    cudaStreamWaitEvent(0, e_u, 0);
    cudaStreamWaitEvent(0, e_s1, 0);

    /* max-sum message passing; qstep(t) pipelined on s2 */
    for (int t = 0; t < NITER; t++) {
        int cur = t & 1, nxt = 1 - cur, ab = t & 1;
        k_msg<<<(Ee*32 + 255)/256, 256>>>(edges, out_u, out_p, cur, nxt);
        if (t >= 2) cudaStreamWaitEvent(0, evQ[t-2], 0);
        k_argmax<<<(Nn*Aa + 255)/256, 256>>>(out_u, nxt, ab);
        cudaEventRecord(evI[t], 0);
        cudaStreamWaitEvent(s2, evI[t], 0);
        k_qstep<<<64, 256, 0, s2>>>(edges, out_u, out_p, ab);
        cudaEventRecord(evQ[t], s2);
    }
    cudaStreamWaitEvent(0, evQ[NITER-1], 0);

    k_final<<<(Nn*Aa + 255)/256, 256>>>(out);
}

// round 7
// speedup vs baseline: 2.5930x; 1.0278x over previous
#include <cuda_runtime.h>
#include <cuda_bf16.h>
#include <math.h>
#include <float.h>

#define Nn   2000
#define Aa   16
#define OBSd 64
#define Hh   128
#define Ee   16000
#define NITER 8
#define IN_DIM 80
#define G3    384
#define E2    (2*Ee)

/* ---------------- scratch (static device globals) ------------------------ */
__device__ __align__(16) float g_inp[Nn*IN_DIM];
__device__ __align__(16) float g_gi[Nn*G3];
__device__ __align__(16) float g_gh[Nn*G3];
__device__ __align__(16) float g_h[Nn*Hh];
__device__ __align__(16) float g_hA[Nn*Hh];
__device__ __align__(16) float g_hB[Nn*Hh];
__device__ __align__(16) float g_ua[Nn*256];
__device__ __align__(16) float g_ub[Nn*256];
__device__ __align__(16) __nv_bfloat16 g_a0h[(size_t)E2*Hh];
__device__ __align__(16) __nv_bfloat16 g_a0l[(size_t)E2*Hh];
__device__ __align__(16) __nv_bfloat16 g_a1h[(size_t)E2*256];
__device__ __align__(16) __nv_bfloat16 g_a1l[(size_t)E2*256];
__device__ __align__(16) __nv_bfloat16 g_a2h[(size_t)E2*256];
__device__ __align__(16) __nv_bfloat16 g_a2l[(size_t)E2*256];
__device__ __align__(16) __nv_bfloat16 g_w1h[256*Hh],  g_w1l[256*Hh];
__device__ __align__(16) __nv_bfloat16 g_w2h[256*256], g_w2l[256*256];
__device__ __align__(16) float g_M[Ee*2*Aa];
__device__ __align__(16) float g_S[2*Nn*Aa];
__device__ int   g_map[Nn*Nn];
__device__ int   g_isrep[Ee];
__device__ int   g_aidx[2][Nn];
__device__ int   g_best[Nn];
__device__ float g_part[64];
__device__ int   g_qctr;
__device__ float g_qmax;

/* ---------------- bf16 split helper ---------------------------------------- */
__device__ __forceinline__ void split2(float v0, float v1, unsigned& h, unsigned& l) {
    __nv_bfloat162 hh = __floats2bfloat162_rn(v0, v1);
    float r0 = v0 - __bfloat162float(hh.x);
    float r1 = v1 - __bfloat162float(hh.y);
    __nv_bfloat162 ll = __floats2bfloat162_rn(r0, r1);
    h = *reinterpret_cast<unsigned*>(&hh);
    l = *reinterpret_cast<unsigned*>(&ll);
}

/* ---------------- init ------------------------------------------------------ */
__global__ void k_init() {
    int idx = blockIdx.x*blockDim.x + threadIdx.x;
    int stride = gridDim.x*blockDim.x;
    for (int i = idx; i < Ee*2*Aa; i += stride) g_M[i]   = 0.f;
    for (int i = idx; i < 2*Nn*Aa; i += stride) g_S[i]   = 0.f;
    for (int i = idx; i < Nn; i += stride)      g_best[i] = -1;
    if (idx == 0) { g_qmax = 0.f; g_qctr = 0; }
}

__global__ void k_clearmap(const int* __restrict__ edges) {
    int e = blockIdx.x*blockDim.x + threadIdx.x;
    if (e >= Ee) return;
    g_map[edges[2*e]*Nn + edges[2*e+1]] = 0x7fffffff;
}

__global__ void k_mapbuild(const int* __restrict__ edges) {
    int e = blockIdx.x*blockDim.x + threadIdx.x;
    if (e >= Ee) return;
    atomicMin(&g_map[edges[2*e]*Nn + edges[2*e+1]], e);
}

__global__ void k_isrep(const int* __restrict__ edges) {
    int e = blockIdx.x*blockDim.x + threadIdx.x;
    if (e >= Ee) return;
    g_isrep[e] = (g_map[edges[2*e]*Nn + edges[2*e+1]] == e) ? 1 : 0;
}

/* ---------------- weight split --------------------------------------------- */
__global__ void k_wsplit(const float* __restrict__ W, int n,
                         __nv_bfloat16* __restrict__ Wh, __nv_bfloat16* __restrict__ Wl) {
    int i = blockIdx.x*blockDim.x + threadIdx.x;
    if (i >= n) return;
    float v = W[i];
    __nv_bfloat16 h = __float2bfloat16(v);
    Wh[i] = h;
    Wl[i] = __float2bfloat16(v - __bfloat162float(h));
}

/* ---------------- encoder input concat ------------------------------------- */
__global__ void k_concat(const float* __restrict__ x, const float* __restrict__ pa) {
    int idx = blockIdx.x*blockDim.x + threadIdx.x;
    if (idx >= Nn*IN_DIM) return;
    int n = idx / IN_DIM, c = idx % IN_DIM;
    g_inp[idx] = (c < OBSd) ? x[n*OBSd + c] : pa[n*Aa + (c - OBSd)];
}

/* ---------------- 128x128x8 double-buffered SGEMM (fp32) ------------------- */
#define BM 128
#define BN 128
#define BK 8

__global__ __launch_bounds__(256,2)
void k_gemm128(const float* __restrict__ X, int lda,
               const float* __restrict__ W, int ldw,
               const float* __restrict__ bias, float* __restrict__ C,
               int M, int N, int K, int relu, float scale, float bias_mult,
               int vec_store)
{
    __shared__ __align__(16) float As[2][BK][BM+4];
    __shared__ __align__(16) float Bs[2][BK][BN+4];
    const int t   = threadIdx.x;
    const int bm  = blockIdx.y * BM;
    const int bn  = blockIdx.x * BN;
    const int lrow = t >> 1;
    const int lcol = (t & 1) << 2;
    const int tx = t & 15, ty = t >> 4;
    const int cx0 = tx << 2, cx1 = 64 + (tx << 2);
    const int ry0 = ty << 2, ry1 = 64 + (ty << 2);

    float acc[8][8];
#pragma unroll
    for (int i = 0; i < 8; i++)
#pragma unroll
        for (int j = 0; j < 8; j++) acc[i][j] = 0.f;

    const bool xok = (bm + lrow) < M;
    const bool wok = (bn + lrow) < N;
    const float* Xp = X + (size_t)(bm + lrow)*lda + lcol;
    const float* Wp = W + (size_t)(bn + lrow)*ldw + lcol;
    const float4 z4 = make_float4(0.f,0.f,0.f,0.f);

    float4 xa = xok ? *reinterpret_cast<const float4*>(Xp) : z4;
    float4 wa = wok ? *reinterpret_cast<const float4*>(Wp) : z4;
    As[0][lcol+0][lrow]=xa.x; As[0][lcol+1][lrow]=xa.y; As[0][lcol+2][lrow]=xa.z; As[0][lcol+3][lrow]=xa.w;
    Bs[0][lcol+0][lrow]=wa.x; Bs[0][lcol+1][lrow]=wa.y; Bs[0][lcol+2][lrow]=wa.z; Bs[0][lcol+3][lrow]=wa.w;
    __syncthreads();

    int buf = 0;
    for (int k0 = 0; k0 < K; k0 += BK) {
        const bool more = (k0 + BK) < K;
        float4 xn = z4, wn = z4;
        if (more) {
            if (xok) xn = *reinterpret_cast<const float4*>(Xp + k0 + BK);
            if (wok) wn = *reinterpret_cast<const float4*>(Wp + k0 + BK);
        }
#pragma unroll
        for (int k = 0; k < BK; k++) {
            float4 a0 = *reinterpret_cast<const float4*>(&As[buf][k][ry0]);
            float4 a1 = *reinterpret_cast<const float4*>(&As[buf][k][ry1]);
            float4 b0 = *reinterpret_cast<const float4*>(&Bs[buf][k][cx0]);
            float4 b1 = *reinterpret_cast<const float4*>(&Bs[buf][k][cx1]);
            float ar[8] = {a0.x,a0.y,a0.z,a0.w,a1.x,a1.y,a1.z,a1.w};
            float br[8] = {b0.x,b0.y,b0.z,b0.w,b1.x,b1.y,b1.z,b1.w};
#pragma unroll
            for (int i = 0; i < 8; i++)
#pragma unroll
                for (int j = 0; j < 8; j++)
                    acc[i][j] = fmaf(ar[i], br[j], acc[i][j]);
        }
        if (more) {
            int nb = buf ^ 1;
            As[nb][lcol+0][lrow]=xn.x; As[nb][lcol+1][lrow]=xn.y; As[nb][lcol+2][lrow]=xn.z; As[nb][lcol+3][lrow]=xn.w;
            Bs[nb][lcol+0][lrow]=wn.x; Bs[nb][lcol+1][lrow]=wn.y; Bs[nb][lcol+2][lrow]=wn.z; Bs[nb][lcol+3][lrow]=wn.w;
            __syncthreads();
            buf = nb;
        }
    }

    float4 bv0 = *reinterpret_cast<const float4*>(&bias[bn + cx0]);
    float4 bv1 = *reinterpret_cast<const float4*>(&bias[bn + cx1]);
#pragma unroll
    for (int ii = 0; ii < 8; ii++) {
        int r = bm + ((ii < 4) ? (ry0 + ii) : (ry1 + ii - 4));
        if (r >= M) continue;
        float o[8];
        o[0]=acc[ii][0]+bias_mult*bv0.x; o[1]=acc[ii][1]+bias_mult*bv0.y;
        o[2]=acc[ii][2]+bias_mult*bv0.z; o[3]=acc[ii][3]+bias_mult*bv0.w;
        o[4]=acc[ii][4]+bias_mult*bv1.x; o[5]=acc[ii][5]+bias_mult*bv1.y;
        o[6]=acc[ii][6]+bias_mult*bv1.z; o[7]=acc[ii][7]+bias_mult*bv1.w;
        if (relu) {
#pragma unroll
            for (int j = 0; j < 8; j++) o[j] = fmaxf(o[j], 0.f);
        }
#pragma unroll
        for (int j = 0; j < 8; j++) o[j] *= scale;
        if (vec_store) {
            *reinterpret_cast<float4*>(&C[(size_t)r*N + bn + cx0]) = make_float4(o[0],o[1],o[2],o[3]);
            *reinterpret_cast<float4*>(&C[(size_t)r*N + bn + cx1]) = make_float4(o[4],o[5],o[6],o[7]);
        } else {
            float* c0 = &C[(size_t)r*N + bn + cx0];
            float* c1 = &C[(size_t)r*N + bn + cx1];
            c0[0]=o[0]; c0[1]=o[1]; c0[2]=o[2]; c0[3]=o[3];
            c1[0]=o[4]; c1[1]=o[5]; c1[2]=o[6]; c1[3]=o[7];
        }
    }
}

/* ---------------- split-bf16 tensor GEMM (mma.sync m16n8k16) --------------- */
#define TBM 128
#define TBN 64
#define TBK 32

#define MMA_BF16(c, a, b) \
    asm volatile("mma.sync.aligned.m16n8k16.row.col.f32.bf16.bf16.f32 " \
        "{%0,%1,%2,%3}, {%4,%5,%6,%7}, {%8,%9}, {%0,%1,%2,%3};" \
        : "+f"((c)[0]), "+f"((c)[1]), "+f"((c)[2]), "+f"((c)[3]) \
        : "r"((a)[0]), "r"((a)[1]), "r"((a)[2]), "r"((a)[3]), "r"((b)[0]), "r"((b)[1]))

__device__ __forceinline__ unsigned lds_bf2(const __nv_bfloat16* p) {
    return *reinterpret_cast<const unsigned*>(p);
}

__global__ __launch_bounds__(256,2)
void k_tgemm(const __nv_bfloat16* __restrict__ Ah, const __nv_bfloat16* __restrict__ Al,
             const __nv_bfloat16* __restrict__ Bh, const __nv_bfloat16* __restrict__ Bl,
             const float* __restrict__ bias, int M, int N, int K,
             __nv_bfloat16* __restrict__ Ch, __nv_bfloat16* __restrict__ Cl)
{
    __shared__ __align__(16) __nv_bfloat16 sAh[TBM][TBK+8];
    __shared__ __align__(16) __nv_bfloat16 sAl[TBM][TBK+8];
    __shared__ __align__(16) __nv_bfloat16 sBh[TBN][TBK+8];
    __shared__ __align__(16) __nv_bfloat16 sBl[TBN][TBK+8];

    const int t = threadIdx.x;
    const int bm = blockIdx.y * TBM;
    const int bn = blockIdx.x * TBN;
    const int wid = t >> 5;
    const int lane = t & 31;
    const int g  = lane >> 2;
    const int tg = lane & 3;
    const int warp_m = (wid & 3) * 32;
    const int warp_n = (wid >> 2) * 32;

    float c[2][4][4];
#pragma unroll
    for (int mi = 0; mi < 2; mi++)
#pragma unroll
        for (int ni = 0; ni < 4; ni++)
#pragma unroll
            for (int q = 0; q < 4; q++) c[mi][ni][q] = 0.f;

    const int ar = t >> 1;
    const int ac = (t & 1) * 16;
    const int br = t >> 2;
    const int bc = (t & 3) * 8;

    for (int kk = 0; kk < K; kk += TBK) {
        {
            uint4 vh0 = *reinterpret_cast<const uint4*>(Ah + (size_t)(bm+ar)*K + kk + ac);
            uint4 vh1 = *reinterpret_cast<const uint4*>(Ah + (size_t)(bm+ar)*K + kk + ac + 8);
            uint4 vl0 = *reinterpret_cast<const uint4*>(Al + (size_t)(bm+ar)*K + kk + ac);
            uint4 vl1 = *reinterpret_cast<const uint4*>(Al + (size_t)(bm+ar)*K + kk + ac + 8);
            *reinterpret_cast<uint4*>(&sAh[ar][ac])     = vh0;
            *reinterpret_cast<uint4*>(&sAh[ar][ac + 8]) = vh1;
            *reinterpret_cast<uint4*>(&sAl[ar][ac])     = vl0;
            *reinterpret_cast<uint4*>(&sAl[ar][ac + 8]) = vl1;
        }
        {
            uint4 wh = *reinterpret_cast<const uint4*>(Bh + (size_t)(bn+br)*K + kk + bc);
            uint4 wl = *reinterpret_cast<const uint4*>(Bl + (size_t)(bn+br)*K + kk + bc);
            *reinterpret_cast<uint4*>(&sBh[br][bc]) = wh;
            *reinterpret_cast<uint4*>(&sBl[br][bc]) = wl;
        }
        __syncthreads();

#pragma unroll
        for (int k16 = 0; k16 < TBK; k16 += 16) {
            unsigned ah[2][4], al[2][4], bh[4][2], bl[4][2];
#pragma unroll
            for (int mi = 0; mi < 2; mi++) {
                int rb = warp_m + mi*16;
                ah[mi][0] = lds_bf2(&sAh[rb+g  ][k16 + 2*tg]);
                ah[mi][1] = lds_bf2(&sAh[rb+g+8][k16 + 2*tg]);
                ah[mi][2] = lds_bf2(&sAh[rb+g  ][k16 + 2*tg + 8]);
                ah[mi][3] = lds_bf2(&sAh[rb+g+8][k16 + 2*tg + 8]);
                al[mi][0] = lds_bf2(&sAl[rb+g  ][k16 + 2*tg]);
                al[mi][1] = lds_bf2(&sAl[rb+g+8][k16 + 2*tg]);
                al[mi][2] = lds_bf2(&sAl[rb+g  ][k16 + 2*tg + 8]);
                al[mi][3] = lds_bf2(&sAl[rb+g+8][k16 + 2*tg + 8]);
            }
#pragma unroll
            for (int ni = 0; ni < 4; ni++) {
                int cb = warp_n + ni*8;
                bh[ni][0] = lds_bf2(&sBh[cb+g][k16 + 2*tg]);
                bh[ni][1] = lds_bf2(&sBh[cb+g][k16 + 2*tg + 8]);
                bl[ni][0] = lds_bf2(&sBl[cb+g][k16 + 2*tg]);
                bl[ni][1] = lds_bf2(&sBl[cb+g][k16 + 2*tg + 8]);
            }
#pragma unroll
            for (int mi = 0; mi < 2; mi++)
#pragma unroll
                for (int ni = 0; ni < 4; ni++) {
                    MMA_BF16(c[mi][ni], ah[mi], bh[ni]);
                    MMA_BF16(c[mi][ni], ah[mi], bl[ni]);
                    MMA_BF16(c[mi][ni], al[mi], bh[ni]);
                }
        }
        __syncthreads();
    }

#pragma unroll
    for (int mi = 0; mi < 2; mi++) {
        int r0 = bm + warp_m + mi*16 + g;
        int r1 = r0 + 8;
#pragma unroll
        for (int ni = 0; ni < 4; ni++) {
            int cb = bn + warp_n + ni*8 + 2*tg;
            float b0 = bias[cb], b1 = bias[cb+1];
            float v0 = fmaxf(c[mi][ni][0] + b0, 0.f);
            float v1 = fmaxf(c[mi][ni][1] + b1, 0.f);
            float v2 = fmaxf(c[mi][ni][2] + b0, 0.f);
            float v3 = fmaxf(c[mi][ni][3] + b1, 0.f);
            unsigned h01, l01, h23, l23;
            split2(v0, v1, h01, l01);
            split2(v2, v3, h23, l23);
            *reinterpret_cast<unsigned*>(&Ch[(size_t)r0*N + cb]) = h01;
            *reinterpret_cast<unsigned*>(&Cl[(size_t)r0*N + cb]) = l01;
            *reinterpret_cast<unsigned*>(&Ch[(size_t)r1*N + cb]) = h23;
            *reinterpret_cast<unsigned*>(&Cl[(size_t)r1*N + cb]) = l23;
        }
    }
}

/* ---------------- skinny GEMM, N=16, fp32 input (u-MLP) -------------------- */
__global__ __launch_bounds__(256,4)
void k_gemm16(const float* __restrict__ X, int lda,
              const float* __restrict__ W, int ldw,
              const float* __restrict__ bias, float* __restrict__ C,
              int M, int K, int relu, float scale)
{
    __shared__ __align__(16) float As[16][BM+4];
    __shared__ float Bs[16][17];
    const int t = threadIdx.x;
    const int bm = blockIdx.x * BM;
    const int arow = t >> 1, acol = (t & 1) << 3;
    const int tx = t & 15, ty = t >> 4;
    const bool xok = (bm + arow) < M;
    const float4 z4 = make_float4(0.f,0.f,0.f,0.f);

    float acc[8];
#pragma unroll
    for (int i = 0; i < 8; i++) acc[i] = 0.f;

    for (int k0 = 0; k0 < K; k0 += 16) {
        float4 v0 = z4, v1 = z4;
        if (xok) {
            v0 = *reinterpret_cast<const float4*>(X + (size_t)(bm+arow)*lda + k0 + acol);
            v1 = *reinterpret_cast<const float4*>(X + (size_t)(bm+arow)*lda + k0 + acol + 4);
        }
        float4 wv = z4;
        int wr = t >> 2, wc = (t & 3) << 2;
        if (t < 64) wv = *reinterpret_cast<const float4*>(W + (size_t)wr*ldw + k0 + wc);
        __syncthreads();
        As[acol+0][arow]=v0.x; As[acol+1][arow]=v0.y; As[acol+2][arow]=v0.z; As[acol+3][arow]=v0.w;
        As[acol+4][arow]=v1.x; As[acol+5][arow]=v1.y; As[acol+6][arow]=v1.z; As[acol+7][arow]=v1.w;
        if (t < 64) { Bs[wc+0][wr]=wv.x; Bs[wc+1][wr]=wv.y; Bs[wc+2][wr]=wv.z; Bs[wc+3][wr]=wv.w; }
        __syncthreads();
#pragma unroll
        for (int k = 0; k < 16; k++) {
            float b = Bs[k][tx];
            float4 a0 = *reinterpret_cast<const float4*>(&As[k][ty*8]);
            float4 a1 = *reinterpret_cast<const float4*>(&As[k][ty*8+4]);
            acc[0]=fmaf(a0.x,b,acc[0]); acc[1]=fmaf(a0.y,b,acc[1]);
            acc[2]=fmaf(a0.z,b,acc[2]); acc[3]=fmaf(a0.w,b,acc[3]);
            acc[4]=fmaf(a1.x,b,acc[4]); acc[5]=fmaf(a1.y,b,acc[5]);
            acc[6]=fmaf(a1.z,b,acc[6]); acc[7]=fmaf(a1.w,b,acc[7]);
        }
        __syncthreads();
    }
    float bb = bias[tx];
#pragma unroll
    for (int i = 0; i < 8; i++) {
        int r = bm + ty*8 + i;
        if (r >= M) continue;
        float v = acc[i] + bb;
        if (relu) v = fmaxf(v, 0.f);
        C[(size_t)r*16 + tx] = v * scale;
    }
}

/* ---------------- fused tail: layer3 (both dirs) + merge + layer4 ---------- */
/* per block: 128 edges. z = relu(W3@a2_ij) + relu(W3@a2_ji);                 */
/* out_p[e] = (W4 @ z + 2*b4) * 0.5/E                                         */
__global__ __launch_bounds__(256,2)
void k_tail(const __nv_bfloat16* __restrict__ Xh, const __nv_bfloat16* __restrict__ Xl,
            const float* __restrict__ W3, const float* __restrict__ b3,
            const float* __restrict__ W4, const float* __restrict__ b4,
            float* __restrict__ out_p)
{
    __shared__ __align__(16) float As[16][BM+4];
    __shared__ float Bs[16][17];
    __shared__ float Z[128][17];
    const int t = threadIdx.x;
    const int base = blockIdx.x * 128;
    const int arow = t >> 1, acol = (t & 1) << 3;
    const int tx = t & 15, ty = t >> 4;

#pragma unroll
    for (int d = 0; d < 2; d++) {
        float acc[8];
#pragma unroll
        for (int i = 0; i < 8; i++) acc[i] = 0.f;
        const size_t roff = (size_t)(base + arow + d*Ee) * 256;

        for (int k0 = 0; k0 < 256; k0 += 16) {
            uint4 uh = *reinterpret_cast<const uint4*>(Xh + roff + k0 + acol);
            uint4 ul = *reinterpret_cast<const uint4*>(Xl + roff + k0 + acol);
            float4 wv = make_float4(0.f,0.f,0.f,0.f);
            int wr = t >> 2, wc = (t & 3) << 2;
            if (t < 64) wv = *reinterpret_cast<const float4*>(W3 + (size_t)wr*256 + k0 + wc);
            __syncthreads();
            {
                const unsigned* ph = reinterpret_cast<const unsigned*>(&uh);
                const unsigned* pl = reinterpret_cast<const unsigned*>(&ul);
#pragma unroll
                for (int q = 0; q < 4; q++) {
                    __nv_bfloat162 hh = *reinterpret_cast<const __nv_bfloat162*>(&ph[q]);
                    __nv_bfloat162 ll = *reinterpret_cast<const __nv_bfloat162*>(&pl[q]);
                    float2 fh = __bfloat1622float2(hh);
                    float2 fl = __bfloat1622float2(ll);
                    As[acol + 2*q    ][arow] = fh.x + fl.x;
                    As[acol + 2*q + 1][arow] = fh.y + fl.y;
                }
            }
            if (t < 64) { Bs[wc+0][wr]=wv.x; Bs[wc+1][wr]=wv.y; Bs[wc+2][wr]=wv.z; Bs[wc+3][wr]=wv.w; }
            __syncthreads();
#pragma unroll
            for (int k = 0; k < 16; k++) {
                float b = Bs[k][tx];
                float4 a0 = *reinterpret_cast<const float4*>(&As[k][ty*8]);
                float4 a1 = *reinterpret_cast<const float4*>(&As[k][ty*8+4]);
                acc[0]=fmaf(a0.x,b,acc[0]); acc[1]=fmaf(a0.y,b,acc[1]);
                acc[2]=fmaf(a0.z,b,acc[2]); acc[3]=fmaf(a0.w,b,acc[3]);
                acc[4]=fmaf(a1.x,b,acc[4]); acc[5]=fmaf(a1.y,b,acc[5]);
                acc[6]=fmaf(a1.z,b,acc[6]); acc[7]=fmaf(a1.w,b,acc[7]);
            }
        }
        float bb = b3[tx];
#pragma unroll
        for (int i = 0; i < 8; i++) {
            float v = fmaxf(acc[i] + bb, 0.f);
            if (d == 0) Z[ty*8 + i][tx] = v;
            else        Z[ty*8 + i][tx] += v;
        }
        __syncthreads();
    }

    /* layer 4: thread t owns output column t */
    float w4r[16];
#pragma unroll
    for (int k = 0; k < 16; k++) w4r[k] = W4[t*16 + k];
    const float bb4 = 2.f * b4[t];
    const float sc = 0.5f / (float)Ee;
    for (int r = 0; r < 128; r++) {
        float s = bb4;
#pragma unroll
        for (int k = 0; k < 16; k++) s = fmaf(Z[r][k], w4r[k], s);
        out_p[(size_t)(base + r)*256 + t] = s * sc;
    }
}

/* ---------------- GRU elementwise ------------------------------------------ */
__global__ void k_gru(const float* __restrict__ hprev, float* __restrict__ out_h) {
    int idx = blockIdx.x*blockDim.x + threadIdx.x;
    if (idx >= Nn*Hh) return;
    int n = idx / Hh, d = idx % Hh;
    const float* gi = g_gi + n*G3;
    const float* gh = g_gh + n*G3;
    float r = 1.f/(1.f + expf(-(gi[d]       + gh[d])));
    float z = 1.f/(1.f + expf(-(gi[Hh+d]    + gh[Hh+d])));
    float t = tanhf(gi[2*Hh+d] + r*gh[2*Hh+d]);
    float h = (1.f - z)*t + z*hprev[idx];
    g_h[idx] = h;
    out_h[idx] = h;
}

/* ---------------- p-layer0: relu(hA[a]+hB[b]+b0) -> split bf16 ------------- */
__global__ void k_edge0(const int* __restrict__ edges, const float* __restrict__ b0) {
    int idx = blockIdx.x*blockDim.x + threadIdx.x;
    if (idx >= E2*32) return;
    int r = idx >> 5;
    int c = (idx & 31) << 2;
    int e = (r < Ee) ? r : r - Ee;
    int i = edges[2*e], j = edges[2*e+1];
    int na = (r < Ee) ? i : j;
    int nb = (r < Ee) ? j : i;
    float4 a = *reinterpret_cast<const float4*>(&g_hA[na*Hh + c]);
    float4 b = *reinterpret_cast<const float4*>(&g_hB[nb*Hh + c]);
    float4 bb = *reinterpret_cast<const float4*>(&b0[c]);
    float v0 = fmaxf(a.x + b.x + bb.x, 0.f);
    float v1 = fmaxf(a.y + b.y + bb.y, 0.f);
    float v2 = fmaxf(a.z + b.z + bb.z, 0.f);
    float v3 = fmaxf(a.w + b.w + bb.w, 0.f);
    unsigned h01, l01, h23, l23;
    split2(v0, v1, h01, l01);
    split2(v2, v3, h23, l23);
    size_t base = (size_t)r*Hh + c;
    *reinterpret_cast<unsigned*>(&g_a0h[base])     = h01;
    *reinterpret_cast<unsigned*>(&g_a0h[base + 2]) = h23;
    *reinterpret_cast<unsigned*>(&g_a0l[base])     = l01;
    *reinterpret_cast<unsigned*>(&g_a0l[base + 2]) = l23;
}

/* ---------------- message update, 2 edges/warp + fused scatter ------------- */
__global__ void k_msg(const int* __restrict__ edges, const float* __restrict__ u,
                      const float* __restrict__ p, int cur, int nxt) {
    int gt = blockIdx.x*blockDim.x + threadIdx.x;
    int w = gt >> 4;                       /* one 16-lane group per edge */
    if (w >= Ee) return;
    if (!g_isrep[w]) return;
    const unsigned gmask = 0xffffu << (threadIdx.x & 16);
    int b = threadIdx.x & 15;
    const float* S  = g_S + cur*Nn*Aa;
    float*       Sn = g_S + nxt*Nn*Aa;
    int i = edges[2*w], j = edges[2*w+1];
    float Mi = g_M[(w*2 + 0)*Aa + b];
    float Mj = g_M[(w*2 + 1)*Aa + b];
    float base_i = u[i*Aa + b] + S[i*Aa + b] - Mi;
    float base_j = u[j*Aa + b] + S[j*Aa + b] - Mj;
    const float* pe = p + (size_t)w*256;
    float mtj = -FLT_MAX, colmax = -FLT_MAX;
#pragma unroll
    for (int a2 = 0; a2 < 16; a2++) {
        float pab = pe[a2*16 + b];
        float bia = __shfl_sync(gmask, base_i, a2, 16);
        mtj    = fmaxf(mtj, pab + bia);
        colmax = fmaxf(colmax, pab);
    }
    float mti = colmax + base_j;
    float s1 = mtj, s2 = mti;
#pragma unroll
    for (int m = 8; m; m >>= 1) {
        s1 += __shfl_xor_sync(gmask, s1, m, 16);
        s2 += __shfl_xor_sync(gmask, s2, m, 16);
    }
    mtj -= s1 * (1.f/16.f);
    mti -= s2 * (1.f/16.f);
    g_M[(w*2 + 1)*Aa + b] = mtj;
    g_M[(w*2 + 0)*Aa + b] = mti;
    atomicAdd(&Sn[i*Aa + b], mti);
    atomicAdd(&Sn[j*Aa + b], mtj);
}

/* ---------------- per-node argmax + zero other S buffer -------------------- */
__global__ void k_argmax(const float* __restrict__ u, int nxt, int ab) {
    int idx = blockIdx.x*blockDim.x + threadIdx.x;
    const float* S = g_S + nxt*Nn*Aa;
    float* Sz = g_S + (1 - nxt)*Nn*Aa;
    if (idx < Nn) {
        float best = -FLT_MAX; int bi = 0;
#pragma unroll
        for (int a = 0; a < Aa; a++) {
            float v = u[idx*Aa + a] + S[idx*Aa + a];
            if (v > best) { best = v; bi = a; }
        }
        g_aidx[ab][idx] = bi;
    }
    if (idx < Nn*Aa) Sz[idx] = 0.f;
}

/* ---------------- q partial sums + fused last-block final reduce ----------- */
__global__ void k_qstep(const int* __restrict__ edges, const float* __restrict__ u,
                        const float* __restrict__ p, int ab) {
    __shared__ float red[256];
    __shared__ int lastdone;
    const int* aidx = g_aidx[ab];
    int tid = threadIdx.x, bid = blockIdx.x;
    int gt = bid*256 + tid;
    float local = 0.f;
    for (int n = gt; n < Nn; n += 64*256) local += u[n*Aa + aidx[n]];
    for (int e = gt; e < Ee; e += 64*256) {
        int i = edges[2*e], j = edges[2*e+1];
        local += p[(size_t)e*256 + aidx[i]*Aa + aidx[j]];
    }
    red[tid] = local;
    __syncthreads();
    for (int s = 128; s > 0; s >>= 1) {
        if (tid < s) red[tid] += red[tid + s];
        __syncthreads();
    }
    if (tid == 0) {
        g_part[bid] = red[0];
        __threadfence();
        int done = atomicAdd(&g_qctr, 1);
        lastdone = (done == 63) ? 1 : 0;
    }
    __syncthreads();
    if (!lastdone) return;
    __shared__ int better;
    if (tid == 0) {
        float q = 0.f;
        for (int k = 0; k < 64; k++) q += g_part[k];
        if (q > g_qmax) { g_qmax = q; better = 1; } else better = 0;
        g_qctr = 0;
    }
    __syncthreads();
    if (better) {
        for (int n = tid; n < Nn; n += 256) g_best[n] = g_aidx[ab][n];
    }
}

/* ---------------- finalize --------------------------------------------------- */
__global__ void k_final(float* __restrict__ out) {
    int idx = blockIdx.x*blockDim.x + threadIdx.x;
    if (idx >= Nn*Aa) return;
    int n = idx >> 4, a = idx & 15;
    out[idx] = (g_best[n] == a) ? 1.f : 0.f;
    if (idx == 0) out[Nn*Aa] = g_qmax;
}

/* ---------------- host ------------------------------------------------------- */
static inline void gemm(cudaStream_t st, const float* X, int lda, const float* W, int ldw,
                        const float* b, float* C, int M, int N, int K,
                        int relu, float scale, float bias_mult, int vec_store) {
    dim3 grid(N/BN, (M + BM - 1)/BM);
    k_gemm128<<<grid, 256, 0, st>>>(X, lda, W, ldw, b, C, M, N, K, relu, scale, bias_mult, vec_store);
}

extern "C" void kernel_launch(void* const* d_in, const int* in_sizes, int n_in,
                              void* d_out, int out_size) {
    const float* x    = (const float*)d_in[0];
    const float* pa   = (const float*)d_in[1];
    const float* st   = (const float*)d_in[2];
    const int*   edges= (const int*)  d_in[3];
    const float* wih  = (const float*)d_in[4];
    const float* whh  = (const float*)d_in[5];
    const float* bih  = (const float*)d_in[6];
    const float* bhh  = (const float*)d_in[7];
    const float* uW0  = (const float*)d_in[8];   const float* ub0 = (const float*)d_in[9];
    const float* uW1  = (const float*)d_in[10];  const float* ub1 = (const float*)d_in[11];
    const float* uW2  = (const float*)d_in[12];  const float* ub2 = (const float*)d_in[13];
    const float* pW0  = (const float*)d_in[14];  const float* pb0 = (const float*)d_in[15];
    const float* pW1  = (const float*)d_in[16];  const float* pb1 = (const float*)d_in[17];
    const float* pW2  = (const float*)d_in[18];  const float* pb2 = (const float*)d_in[19];
    const float* pW3  = (const float*)d_in[20];  const float* pb3 = (const float*)d_in[21];
    const float* pW4  = (const float*)d_in[22];  const float* pb4 = (const float*)d_in[23];

    float* out   = (float*)d_out;
    float* out_u = out + Nn*Aa + 1;
    float* out_p = out_u + Nn*Aa;
    float* out_h = out_p + (size_t)Ee*Aa*Aa;

    float *inp_, *gi_, *gh_, *h_, *hA_, *hB_, *ua_, *ub_;
    __nv_bfloat16 *a0h_, *a0l_, *a1h_, *a1l_, *a2h_, *a2l_, *w1h_, *w1l_, *w2h_, *w2l_;
    cudaGetSymbolAddress((void**)&inp_,  g_inp);
    cudaGetSymbolAddress((void**)&gi_,   g_gi);
    cudaGetSymbolAddress((void**)&gh_,   g_gh);
    cudaGetSymbolAddress((void**)&h_,    g_h);
    cudaGetSymbolAddress((void**)&hA_,   g_hA);
    cudaGetSymbolAddress((void**)&hB_,   g_hB);
    cudaGetSymbolAddress((void**)&ua_,   g_ua);
    cudaGetSymbolAddress((void**)&ub_,   g_ub);
    cudaGetSymbolAddress((void**)&a0h_,  g_a0h);
    cudaGetSymbolAddress((void**)&a0l_,  g_a0l);
    cudaGetSymbolAddress((void**)&a1h_,  g_a1h);
    cudaGetSymbolAddress((void**)&a1l_,  g_a1l);
    cudaGetSymbolAddress((void**)&a2h_,  g_a2h);
    cudaGetSymbolAddress((void**)&a2l_,  g_a2l);
    cudaGetSymbolAddress((void**)&w1h_,  g_w1h);
    cudaGetSymbolAddress((void**)&w1l_,  g_w1l);
    cudaGetSymbolAddress((void**)&w2h_,  g_w2h);
    cudaGetSymbolAddress((void**)&w2l_,  g_w2l);

    static cudaStream_t s1 = 0, s2 = 0, s3 = 0;
    static cudaEvent_t e0 = 0, e_gh, e_gru, e_u, e_hb, e_s1, e_w, evI[NITER], evQ[NITER];
    if (!e0) {
        cudaStreamCreateWithFlags(&s1, cudaStreamNonBlocking);
        cudaStreamCreateWithFlags(&s2, cudaStreamNonBlocking);
        cudaStreamCreateWithFlags(&s3, cudaStreamNonBlocking);
        cudaEventCreateWithFlags(&e0,   cudaEventDisableTiming);
        cudaEventCreateWithFlags(&e_gh, cudaEventDisableTiming);
        cudaEventCreateWithFlags(&e_gru,cudaEventDisableTiming);
        cudaEventCreateWithFlags(&e_u,  cudaEventDisableTiming);
        cudaEventCreateWithFlags(&e_hb, cudaEventDisableTiming);
        cudaEventCreateWithFlags(&e_s1, cudaEventDisableTiming);
        cudaEventCreateWithFlags(&e_w,  cudaEventDisableTiming);
        for (int t = 0; t < NITER; t++) {
            cudaEventCreateWithFlags(&evI[t], cudaEventDisableTiming);
            cudaEventCreateWithFlags(&evQ[t], cudaEventDisableTiming);
        }
    }

    /* fork */
    cudaEventRecord(e0, 0);
    cudaStreamWaitEvent(s1, e0, 0);
    cudaStreamWaitEvent(s2, e0, 0);
    cudaStreamWaitEvent(s3, e0, 0);

    /* s1: MP state init + duplicate-edge dedup */
    k_init<<<1024, 256, 0, s1>>>();
    k_clearmap<<<(Ee + 255)/256, 256, 0, s1>>>(edges);
    k_mapbuild<<<(Ee + 255)/256, 256, 0, s1>>>(edges);
    k_isrep<<<(Ee + 255)/256, 256, 0, s1>>>(edges);
    cudaEventRecord(e_s1, s1);

    /* s3: weight splits */
    k_wsplit<<<(256*Hh + 255)/256, 256, 0, s3>>>(pW1, 256*Hh, w1h_, w1l_);
    k_wsplit<<<(256*256 + 255)/256, 256, 0, s3>>>(pW2, 256*256, w2h_, w2l_);
    cudaEventRecord(e_w, s3);

    /* s2: gh GEMM */
    gemm(s2, st, Hh, whh, Hh, bhh, gh_, Nn, G3, Hh, 0, 1.f, 1.f, 1);
    cudaEventRecord(e_gh, s2);

    /* 0: concat + gi GEMM, then GRU */
    k_concat<<<(Nn*IN_DIM + 255)/256, 256>>>(x, pa);
    gemm(0, inp_, IN_DIM, wih, IN_DIM, bih, gi_, Nn, G3, IN_DIM, 0, 1.f, 1.f, 1);
    cudaStreamWaitEvent(0, e_gh, 0);
    k_gru<<<(Nn*Hh + 255)/256, 256>>>(st, out_h);
    cudaEventRecord(e_gru, 0);

    /* s2: utility MLP */
    cudaStreamWaitEvent(s2, e_gru, 0);
    gemm(s2, h_,  Hh,  uW0, Hh,  ub0, ua_, Nn, 256, Hh,  1, 1.f, 1.f, 1);
    gemm(s2, ua_, 256, uW1, 256, ub1, ub_, Nn, 256, 256, 1, 1.f, 1.f, 1);
    k_gemm16<<<(Nn + BM - 1)/BM, 256, 0, s2>>>(ub_, 256, uW2, 256, ub2, out_u, Nn, 256, 0, 1.f/(float)Nn);
    cudaEventRecord(e_u, s2);

    /* s3: hB GEMM */
    cudaStreamWaitEvent(s3, e_gru, 0);
    gemm(s3, h_, Hh, pW0 + Hh, 2*Hh, pb0, hB_, Nn, Hh, Hh, 0, 1.f, 0.f, 1);
    cudaEventRecord(e_hb, s3);

    /* 0: hA GEMM, edge0 (split), tensor layers 1-2, fused tail */
    gemm(0, h_, Hh, pW0, 2*Hh, pb0, hA_, Nn, Hh, Hh, 0, 1.f, 0.f, 1);
    cudaStreamWaitEvent(0, e_hb, 0);
    k_edge0<<<(E2*32 + 255)/256, 256>>>(edges, pb0);
    cudaStreamWaitEvent(0, e_w, 0);
    {
        dim3 g1(256/TBN, E2/TBM);
        k_tgemm<<<g1, 256>>>(a0h_, a0l_, w1h_, w1l_, pb1, E2, 256, Hh,  a1h_, a1l_);
        k_tgemm<<<g1, 256>>>(a1h_, a1l_, w2h_, w2l_, pb2, E2, 256, 256, a2h_, a2l_);
    }
    k_tail<<<Ee/128, 256>>>(a2h_, a2l_, pW3, pb3, pW4, pb4, out_p);

    /* join */
    cudaStreamWaitEvent(0, e_u, 0);
    cudaStreamWaitEvent(0, e_s1, 0);

    /* max-sum message passing; qstep(t) pipelined on s2 */
    for (int t = 0; t < NITER; t++) {
        int cur = t & 1, nxt = 1 - cur, ab = t & 1;
        k_msg<<<(Ee*16 + 255)/256, 256>>>(edges, out_u, out_p, cur, nxt);
        if (t >= 2) cudaStreamWaitEvent(0, evQ[t-2], 0);
        k_argmax<<<(Nn*Aa + 255)/256, 256>>>(out_u, nxt, ab);
        cudaEventRecord(evI[t], 0);
        cudaStreamWaitEvent(s2, evI[t], 0);
        k_qstep<<<64, 256, 0, s2>>>(edges, out_u, out_p, ab);
        cudaEventRecord(evQ[t], s2);
    }
    cudaStreamWaitEvent(0, evQ[NITER-1], 0);

    k_final<<<(Nn*Aa + 255)/256, 256>>>(out);
}